// round 14
// baseline (speedup 1.0000x reference)
#include <cuda_runtime.h>
#include <cuda_bf16.h>
#include <cstdint>

// ---------------------------------------------------------------------------
// HiroLRAN: encoder(t=0) -> rank-16 scan-as-GEMM (bf16 3-product, triangular
// K-cut) -> fused fix+split -> decoder (bf16 3-product). occ=2 on mma_gemm.
// R14: local GEMM split (s=31 first) + carry chain overlapped on 3rd stream,
//      bf16 split fused into carry kernel.
// ---------------------------------------------------------------------------

#define Bsz 64
#define Tt 1024
#define Din 288
#define LAT 256
#define ENCD 512
#define NROWS (Bsz * Tt)   // 65536
#define PADK 40            // padded K-stride (elements) for ldmatrix tiles

// scratch (device globals: no allocations allowed)
__device__ float g_ZB[(size_t)NROWS * LAT];
__device__ float g_H1[(size_t)NROWS * ENCD];     // aliased: B1 hi|lo bf16
__device__ float g_H2[(size_t)NROWS * ENCD];     // aliased: B2 hi|lo bf16
__device__ float g_Apow[33 * LAT * LAT];         // A^1..A^32 at idx 1..32
__device__ float g_h1e[Bsz * ENCD];
__device__ float g_h2e[Bsz * ENCD];
__device__ float g_z0[Bsz * LAT];
__device__ float g_G[32 * 16 * 256];             // G_r = B A^r
__device__ __nv_bfloat16 g_AZh[(size_t)NROWS * LAT];
__device__ __nv_bfloat16 g_AZl[(size_t)NROWS * LAT];
__device__ __nv_bfloat16 g_W1h[ENCD * LAT], g_W1l[ENCD * LAT];   // N x K
__device__ __nv_bfloat16 g_W2h[ENCD * ENCD], g_W2l[ENCD * ENCD];
__device__ __nv_bfloat16 g_W3h[LAT * ENCD], g_W3l[LAT * ENCD];
__device__ __nv_bfloat16 g_Uh[2048 * 512], g_Ul[2048 * 512];     // gathered u
__device__ __nv_bfloat16 g_Wlh[8192 * 512], g_Wll[8192 * 512];   // Toeplitz G
__device__ __nv_bfloat16 g_Wfh[8192 * 256], g_Wfl[8192 * 256];   // [A^1..A^32]
__device__ __nv_bfloat16 g_Ch[2048 * 256], g_Cl[2048 * 256];     // split carry

// ---- async copy helpers -----------------------------------------------------
__device__ __forceinline__ uint32_t smem_u32(const void* p) {
    return (uint32_t)__cvta_generic_to_shared(p);
}
__device__ __forceinline__ void cpa16s(uint32_t saddr, const void* gsrc) {
    asm volatile("cp.async.ca.shared.global [%0], [%1], 16;\n" :: "r"(saddr), "l"(gsrc));
}
__device__ __forceinline__ void cpa_commit() {
    asm volatile("cp.async.commit_group;\n");
}
__device__ __forceinline__ void cpa_wait0() {
    asm volatile("cp.async.wait_group 0;\n" ::: "memory");
}
__device__ __forceinline__ void cpa_wait1() {
    asm volatile("cp.async.wait_group 1;\n" ::: "memory");
}

// ---- warp-level mma helpers ---------------------------------------------------
__device__ __forceinline__ void ldsm4(uint32_t addr, uint32_t& r0, uint32_t& r1,
                                      uint32_t& r2, uint32_t& r3) {
    asm volatile("ldmatrix.sync.aligned.m8n8.x4.shared.b16 {%0,%1,%2,%3}, [%4];"
                 : "=r"(r0), "=r"(r1), "=r"(r2), "=r"(r3) : "r"(addr));
}
__device__ __forceinline__ void mma16816(float* c, const uint32_t* a,
                                         const uint32_t* b) {
    asm volatile(
        "mma.sync.aligned.m16n8k16.row.col.f32.bf16.bf16.f32 "
        "{%0,%1,%2,%3}, {%4,%5,%6,%7}, {%8,%9}, {%0,%1,%2,%3};"
        : "+f"(c[0]), "+f"(c[1]), "+f"(c[2]), "+f"(c[3])
        : "r"(a[0]), "r"(a[1]), "r"(a[2]), "r"(a[3]), "r"(b[0]), "r"(b[1]));
}

// ---------------------------------------------------------------------------
// mma.sync split-bf16 GEMM. 128x128 CTA tile, 8 warps (2x4), warp tile 64x32,
// BK=32 double-buffered; 3 products (hh, hl, lh), fp32 accumulate. occ=2.
// OUT 0: dense hi/lo bf16 out (+bias, +act)
// OUT 1: dense fp32 out (+bias)
// OUT 2: scatter STORE fp32 -> g_ZB (local scan; triangular K-cut)
// OUT 3: scatter: read g_ZB, add, emit split bf16 -> g_AZh/g_AZl (fused fix)
// xoff: column-block offset (for split local launches).
// ---------------------------------------------------------------------------
#define STAGE_ELEMS (4 * 128 * PADK)
#define MMA_SMEM (2 * STAGE_ELEMS * 2)   // 81920 B

template<int ACT, int OUT>
__global__ __launch_bounds__(256, 2)
void mma_gemm(const __nv_bfloat16* __restrict__ Ah, const __nv_bfloat16* __restrict__ Al,
              const __nv_bfloat16* __restrict__ Bh, const __nv_bfloat16* __restrict__ Bl,
              const float* __restrict__ bias,
              __nv_bfloat16* __restrict__ oHi, __nv_bfloat16* __restrict__ oLo,
              float* __restrict__ oF, int N, int K, int xoff)
{
    extern __shared__ __align__(16) __nv_bfloat16 smem[];
    const int tid  = threadIdx.x;
    const int warp = tid >> 5;
    const int lane = tid & 31;
    const int crow = blockIdx.y * 128;
    const int ccol = (blockIdx.x + xoff) * 128;
    const int mo = (warp >> 2) * 64;
    const int no = (warp & 3) * 32;

    const __nv_bfloat16* gsrc[4] = {
        Ah + (size_t)crow * K, Al + (size_t)crow * K,
        Bh + (size_t)ccol * K, Bl + (size_t)ccol * K };

    auto load_chunk = [&](int s, int kc) {
#pragma unroll
        for (int q = 0; q < 4; q++) {
            const __nv_bfloat16* src = gsrc[q] + kc * 32;
            __nv_bfloat16* dstb = smem + s * STAGE_ELEMS + q * 128 * PADK;
#pragma unroll
            for (int t = 0; t < 2; t++) {
                int g = tid + t * 256;
                int row = g >> 2, c = g & 3;
                cpa16s(smem_u32(dstb + row * PADK + c * 8),
                       src + (size_t)row * K + c * 8);
            }
        }
        cpa_commit();
    };

    float acc[4][4][4];
#pragma unroll
    for (int i = 0; i < 4; i++)
#pragma unroll
        for (int j = 0; j < 4; j++)
#pragma unroll
            for (int v = 0; v < 4; v++) acc[i][j][v] = 0.f;

    // triangular K-cut for the local-scan GEMM
    int Keff = K;
    if (OUT == 2) {
        int s = ccol >> 8;
        int kneed = 16 * (s + 1);
        Keff = (kneed + 31) & ~31;
        if (Keff > K) Keff = K;
    }
    const int nch = Keff / 32;

    load_chunk(0, 0);
    if (nch > 1) load_chunk(1, 1);

    const int a_rowsel = lane & 15;
    const int a_colsel = (lane >> 4) << 3;
    const int b_rowsel = ((lane >> 4) << 3) + (lane & 7);
    const int b_colsel = ((lane >> 3) & 1) << 3;

    for (int i = 0; i < nch; i++) {
        const int s = i & 1;
        if (i + 1 < nch) cpa_wait1(); else cpa_wait0();
        __syncthreads();
        const uint32_t stb = smem_u32(smem) + s * STAGE_ELEMS * 2;
        const uint32_t bAh = stb;
        const uint32_t bAl = stb + 128 * PADK * 2;
        const uint32_t bBh = stb + 2 * 128 * PADK * 2;
        const uint32_t bBl = stb + 3 * 128 * PADK * 2;
#pragma unroll
        for (int kk = 0; kk < 2; kk++) {
            const int kc = kk * 16;
            uint32_t a[4][4], b[4][2], bl[4][2];
#pragma unroll
            for (int it = 0; it < 4; it++) {
                int row = mo + it * 16 + a_rowsel;
                ldsm4(bAh + (row * PADK + kc + a_colsel) * 2,
                      a[it][0], a[it][1], a[it][2], a[it][3]);
            }
#pragma unroll
            for (int jj = 0; jj < 2; jj++) {
                int row = no + jj * 16 + b_rowsel;
                ldsm4(bBh + (row * PADK + kc + b_colsel) * 2,
                      b[2 * jj][0], b[2 * jj][1], b[2 * jj + 1][0], b[2 * jj + 1][1]);
            }
#pragma unroll
            for (int it = 0; it < 4; it++)
#pragma unroll
                for (int jt = 0; jt < 4; jt++) mma16816(acc[it][jt], a[it], b[jt]);
#pragma unroll
            for (int jj = 0; jj < 2; jj++) {
                int row = no + jj * 16 + b_rowsel;
                ldsm4(bBl + (row * PADK + kc + b_colsel) * 2,
                      bl[2 * jj][0], bl[2 * jj][1], bl[2 * jj + 1][0], bl[2 * jj + 1][1]);
            }
#pragma unroll
            for (int it = 0; it < 4; it++)
#pragma unroll
                for (int jt = 0; jt < 4; jt++) mma16816(acc[it][jt], a[it], bl[jt]);
#pragma unroll
            for (int it = 0; it < 4; it++) {
                int row = mo + it * 16 + a_rowsel;
                ldsm4(bAl + (row * PADK + kc + a_colsel) * 2,
                      a[it][0], a[it][1], a[it][2], a[it][3]);
            }
#pragma unroll
            for (int it = 0; it < 4; it++)
#pragma unroll
                for (int jt = 0; jt < 4; jt++) mma16816(acc[it][jt], a[it], b[jt]);
        }
        __syncthreads();
        if (i + 2 < nch) load_chunk(s, i + 2);
    }

#pragma unroll
    for (int it = 0; it < 4; it++) {
#pragma unroll
        for (int jt = 0; jt < 4; jt++) {
            const int r0 = crow + mo + it * 16 + (lane >> 2);
            const int gc = ccol + no + jt * 8 + (lane & 3) * 2;
            float v00 = acc[it][jt][0], v01 = acc[it][jt][1];
            float v10 = acc[it][jt][2], v11 = acc[it][jt][3];
            if (OUT <= 1) {
                const float b0 = bias[gc], b1 = bias[gc + 1];
                v00 += b0; v01 += b1; v10 += b0; v11 += b1;
                if (ACT) {
                    v00 = (v00 >= 0.f) ? v00 : 0.01f * v00;
                    v01 = (v01 >= 0.f) ? v01 : 0.01f * v01;
                    v10 = (v10 >= 0.f) ? v10 : 0.01f * v10;
                    v11 = (v11 >= 0.f) ? v11 : 0.01f * v11;
                }
            }
            if (OUT == 0) {
                __nv_bfloat16 h00 = __float2bfloat16(v00), h01 = __float2bfloat16(v01);
                __nv_bfloat16 h10 = __float2bfloat16(v10), h11 = __float2bfloat16(v11);
                *reinterpret_cast<__nv_bfloat162*>(oHi + (size_t)r0 * N + gc) =
                    __nv_bfloat162(h00, h01);
                *reinterpret_cast<__nv_bfloat162*>(oHi + (size_t)(r0 + 8) * N + gc) =
                    __nv_bfloat162(h10, h11);
                *reinterpret_cast<__nv_bfloat162*>(oLo + (size_t)r0 * N + gc) =
                    __nv_bfloat162(__float2bfloat16(v00 - __bfloat162float(h00)),
                                   __float2bfloat16(v01 - __bfloat162float(h01)));
                *reinterpret_cast<__nv_bfloat162*>(oLo + (size_t)(r0 + 8) * N + gc) =
                    __nv_bfloat162(__float2bfloat16(v10 - __bfloat162float(h10)),
                                   __float2bfloat16(v11 - __bfloat162float(h11)));
            } else if (OUT == 1) {
                *reinterpret_cast<float2*>(oF + (size_t)r0 * N + gc) =
                    make_float2(v00, v01);
                *reinterpret_cast<float2*>(oF + (size_t)(r0 + 8) * N + gc) =
                    make_float2(v10, v11);
            } else {
                const int s  = gc >> 8;
                const int j  = gc & 255;
                const int c  = r0 >> 6;
                const int b0 = r0 & 63;
                const int t  = c * 32 + s;
                size_t i0 = ((size_t)b0 * Tt + t) * 256 + j;
                size_t i1 = ((size_t)(b0 + 8) * Tt + t) * 256 + j;
                if (OUT == 2) {
                    *reinterpret_cast<float2*>(&g_ZB[i0]) = make_float2(v00, v01);
                    *reinterpret_cast<float2*>(&g_ZB[i1]) = make_float2(v10, v11);
                } else {
                    float2 z0 = *reinterpret_cast<const float2*>(&g_ZB[i0]);
                    float2 z1 = *reinterpret_cast<const float2*>(&g_ZB[i1]);
                    float w00 = z0.x + v00, w01 = z0.y + v01;
                    float w10 = z1.x + v10, w11 = z1.y + v11;
                    __nv_bfloat16 h00 = __float2bfloat16(w00), h01 = __float2bfloat16(w01);
                    __nv_bfloat16 h10 = __float2bfloat16(w10), h11 = __float2bfloat16(w11);
                    *reinterpret_cast<__nv_bfloat162*>(&g_AZh[i0]) = __nv_bfloat162(h00, h01);
                    *reinterpret_cast<__nv_bfloat162*>(&g_AZh[i1]) = __nv_bfloat162(h10, h11);
                    *reinterpret_cast<__nv_bfloat162*>(&g_AZl[i0]) = __nv_bfloat162(
                        __float2bfloat16(w00 - __bfloat162float(h00)),
                        __float2bfloat16(w01 - __bfloat162float(h01)));
                    *reinterpret_cast<__nv_bfloat162*>(&g_AZl[i1]) = __nv_bfloat162(
                        __float2bfloat16(w10 - __bfloat162float(h10)),
                        __float2bfloat16(w11 - __bfloat162float(h11)));
                }
            }
        }
    }
}

// split + transpose weights: W (K x N fp32) -> hi/lo (N x K bf16)
__global__ void split_w(const float* __restrict__ W, int K, int N,
                        __nv_bfloat16* __restrict__ hi, __nv_bfloat16* __restrict__ lo)
{
    int idx = blockIdx.x * 256 + threadIdx.x;
    if (idx >= K * N) return;
    int k = idx / N, n = idx % N;
    float v = W[idx];
    __nv_bfloat16 h = __float2bfloat16(v);
    hi[(size_t)n * K + k] = h;
    lo[(size_t)n * K + k] = __float2bfloat16(v - __bfloat162float(h));
}

// gather u slices -> U[2048 x 512] split bf16
__global__ void gatherU(const float* __restrict__ in)
{
    int idx = blockIdx.x * 256 + threadIdx.x;
    if (idx >= 2048 * 512) return;
    int m = idx >> 9, k = idx & 511;
    int c = m >> 6, b = m & 63;
    int j = k >> 4, i = k & 15;
    float v = in[((size_t)b * Tt + c * 32 + j) * Din + 272 + i];
    __nv_bfloat16 h = __float2bfloat16(v);
    g_Uh[idx] = h;
    g_Ul[idx] = __float2bfloat16(v - __bfloat162float(h));
}

// G_r = B_w @ A^r (r=0..31)
__global__ void buildG(const float* __restrict__ Bw)
{
    const int r = blockIdx.x;
    const int n = threadIdx.x;
    if (r == 0) {
        for (int i = 0; i < 16; i++)
            g_G[i * 256 + n] = Bw[i * 256 + n];
        return;
    }
    const float* Ar = g_Apow + (size_t)r * 65536;
    float acc[16];
#pragma unroll
    for (int i = 0; i < 16; i++) acc[i] = 0.f;
    for (int m = 0; m < 256; m++) {
        float a = Ar[m * 256 + n];
#pragma unroll
        for (int i = 0; i < 16; i++)
            acc[i] = fmaf(Bw[i * 256 + m], a, acc[i]);
    }
#pragma unroll
    for (int i = 0; i < 16; i++)
        g_G[(r * 16 + i) * 256 + n] = acc[i];
}

__global__ void buildWlocal()
{
    int idx = blockIdx.x * 256 + threadIdx.x;
    if (idx >= 8192 * 512) return;
    int n = idx >> 9, k = idx & 511;
    int s = n >> 8, col = n & 255, j = k >> 4, i = k & 15;
    int r = s - j;
    float v = (r >= 0) ? g_G[(r * 16 + i) * 256 + col] : 0.f;
    __nv_bfloat16 h = __float2bfloat16(v);
    g_Wlh[idx] = h;
    g_Wll[idx] = __float2bfloat16(v - __bfloat162float(h));
}

__global__ void buildWfix()
{
    int idx = blockIdx.x * 256 + threadIdx.x;
    if (idx >= 8192 * 256) return;
    int n = idx >> 8, k = idx & 255;
    int s = n >> 8, col = n & 255;
    float v = g_Apow[(size_t)(s + 1) * 65536 + k * 256 + col];
    __nv_bfloat16 h = __float2bfloat16(v);
    g_Wfh[idx] = h;
    g_Wfl[idx] = __float2bfloat16(v - __bfloat162float(h));
}

// ---------------------------------------------------------------------------
// Small-M GEMM (encoder, M=64)
// ---------------------------------------------------------------------------
__global__ __launch_bounds__(256)
void gemm_m64(const float* __restrict__ A, long long lda,
              const float* __restrict__ W,
              const float* __restrict__ bias,
              float* __restrict__ C,
              int N, int K, int act)
{
    __shared__ __align__(16) float As[2][16][64];
    __shared__ __align__(16) float Ws[2][16][64];
    const int tid  = threadIdx.x;
    const int ccol = blockIdx.x * 64;
    const int ar = tid >> 2, ak = (tid & 3) * 4;
    const int wr = tid >> 4, wc = (tid & 15) * 4;
    const int ty = tid >> 4, tx = tid & 15;
    float acc[4][4] = {};

    float4 av = *reinterpret_cast<const float4*>(A + (size_t)ar * lda + ak);
    float4 wv = *reinterpret_cast<const float4*>(W + (size_t)wr * N + ccol + wc);
    As[0][ak + 0][ar] = av.x; As[0][ak + 1][ar] = av.y;
    As[0][ak + 2][ar] = av.z; As[0][ak + 3][ar] = av.w;
    *reinterpret_cast<float4*>(&Ws[0][wr][wc]) = wv;
    __syncthreads();

    int buf = 0;
    for (int k0 = 0; k0 < K; k0 += 16) {
        const bool next = (k0 + 16) < K;
        if (next) {
            av = *reinterpret_cast<const float4*>(A + (size_t)ar * lda + k0 + 16 + ak);
            wv = *reinterpret_cast<const float4*>(W + (size_t)(k0 + 16 + wr) * N + ccol + wc);
        }
#pragma unroll
        for (int k = 0; k < 16; k++) {
            float4 a4 = *reinterpret_cast<const float4*>(&As[buf][k][ty * 4]);
            float4 w4 = *reinterpret_cast<const float4*>(&Ws[buf][k][tx * 4]);
            float ar_[4] = {a4.x, a4.y, a4.z, a4.w};
            float wr_[4] = {w4.x, w4.y, w4.z, w4.w};
#pragma unroll
            for (int i = 0; i < 4; i++)
#pragma unroll
                for (int j = 0; j < 4; j++)
                    acc[i][j] = fmaf(ar_[i], wr_[j], acc[i][j]);
        }
        if (next) {
            As[buf ^ 1][ak + 0][ar] = av.x; As[buf ^ 1][ak + 1][ar] = av.y;
            As[buf ^ 1][ak + 2][ar] = av.z; As[buf ^ 1][ak + 3][ar] = av.w;
            *reinterpret_cast<float4*>(&Ws[buf ^ 1][wr][wc]) = wv;
        }
        __syncthreads();
        buf ^= 1;
    }
    float b4[4];
#pragma unroll
    for (int j = 0; j < 4; j++) b4[j] = bias[ccol + tx * 4 + j];
#pragma unroll
    for (int i = 0; i < 4; i++) {
        float o[4];
#pragma unroll
        for (int j = 0; j < 4; j++) {
            float v = acc[i][j] + b4[j];
            if (act) v = (v >= 0.f) ? v : 0.01f * v;
            o[j] = v;
        }
        *reinterpret_cast<float4*>(C + (size_t)(ty * 4 + i) * N + ccol + tx * 4) =
            make_float4(o[0], o[1], o[2], o[3]);
    }
}

__global__ void powinit_kernel(const float* __restrict__ A)
{
    const int i = blockIdx.x * 256 + threadIdx.x;
    g_Apow[65536 + i] = A[i];
}

// Apow[half+q] = Apow[half] @ Apow[q]; register-double-buffered loads
__global__ __launch_bounds__(256)
void pow_gemm(int half)
{
    const int q = blockIdx.z + 1;
    const float* S1 = g_Apow + (size_t)half * 65536;
    const float* S2 = g_Apow + (size_t)q * 65536;
    float* D = g_Apow + (size_t)(half + q) * 65536;
    const int ib = blockIdx.y * 64, jb = blockIdx.x * 64;
    __shared__ __align__(16) float As[2][16][64];
    __shared__ __align__(16) float Bs[2][16][64];
    const int tid = threadIdx.x;
    const int ar = tid >> 2, ak = (tid & 3) * 4;
    const int wr = tid >> 4, wc = (tid & 15) * 4;
    const int ty = tid >> 4, tx = tid & 15;
    float acc[4][4] = {};

    float4 av = *reinterpret_cast<const float4*>(S1 + (size_t)(ib + ar) * 256 + ak);
    float4 wv = *reinterpret_cast<const float4*>(S2 + (size_t)wr * 256 + jb + wc);
    As[0][ak + 0][ar] = av.x; As[0][ak + 1][ar] = av.y;
    As[0][ak + 2][ar] = av.z; As[0][ak + 3][ar] = av.w;
    *reinterpret_cast<float4*>(&Bs[0][wr][wc]) = wv;
    __syncthreads();

    int buf = 0;
    for (int k0 = 0; k0 < 256; k0 += 16) {
        const bool next = (k0 + 16) < 256;
        if (next) {
            av = *reinterpret_cast<const float4*>(S1 + (size_t)(ib + ar) * 256 + k0 + 16 + ak);
            wv = *reinterpret_cast<const float4*>(S2 + (size_t)(k0 + 16 + wr) * 256 + jb + wc);
        }
#pragma unroll
        for (int k = 0; k < 16; k++) {
            float4 a4 = *reinterpret_cast<const float4*>(&As[buf][k][ty * 4]);
            float4 w4 = *reinterpret_cast<const float4*>(&Bs[buf][k][tx * 4]);
            float ar_[4] = {a4.x, a4.y, a4.z, a4.w};
            float wr_[4] = {w4.x, w4.y, w4.z, w4.w};
#pragma unroll
            for (int i = 0; i < 4; i++)
#pragma unroll
                for (int j = 0; j < 4; j++)
                    acc[i][j] = fmaf(ar_[i], wr_[j], acc[i][j]);
        }
        if (next) {
            As[buf ^ 1][ak + 0][ar] = av.x; As[buf ^ 1][ak + 1][ar] = av.y;
            As[buf ^ 1][ak + 2][ar] = av.z; As[buf ^ 1][ak + 3][ar] = av.w;
            *reinterpret_cast<float4*>(&Bs[buf ^ 1][wr][wc]) = wv;
        }
        __syncthreads();
        buf ^= 1;
    }
#pragma unroll
    for (int i = 0; i < 4; i++)
        *reinterpret_cast<float4*>(D + (size_t)(ib + ty * 4 + i) * 256 + jb + tx * 4) =
            make_float4(acc[i][0], acc[i][1], acc[i][2], acc[i][3]);
}

// carry chain: 64 blocks (1 batch each), 4-way accumulators, unroll 4;
// fp32 chain in smem/regs, emits bf16 hi/lo splits directly (fused split_bf).
__global__ void carry_chain64(const float* __restrict__ z0)
{
    const int b = blockIdx.x;
    const int j = threadIdx.x;
    __shared__ float cp[256];
    float cur = z0[b * 256 + j];
    cp[j] = cur;
    {
        __nv_bfloat16 h = __float2bfloat16(cur);
        g_Ch[(size_t)b * 256 + j] = h;
        g_Cl[(size_t)b * 256 + j] = __float2bfloat16(cur - __bfloat162float(h));
    }
    __syncthreads();
    const float* A32 = g_Apow + (size_t)32 * 65536;
    for (int c = 1; c < 32; c++) {
        float s0 = g_ZB[((size_t)b * Tt + c * 32 - 1) * 256 + j];
        float s1 = 0.f, s2 = 0.f, s3 = 0.f;
#pragma unroll 4
        for (int k = 0; k < 256; k += 4) {
            s0 = fmaf(cp[k + 0], A32[(size_t)(k + 0) * 256 + j], s0);
            s1 = fmaf(cp[k + 1], A32[(size_t)(k + 1) * 256 + j], s1);
            s2 = fmaf(cp[k + 2], A32[(size_t)(k + 2) * 256 + j], s2);
            s3 = fmaf(cp[k + 3], A32[(size_t)(k + 3) * 256 + j], s3);
        }
        float a = (s0 + s1) + (s2 + s3);
        __syncthreads();
        cp[j] = a;
        __nv_bfloat16 h = __float2bfloat16(a);
        g_Ch[((size_t)c * 64 + b) * 256 + j] = h;
        g_Cl[((size_t)c * 64 + b) * 256 + j] = __float2bfloat16(a - __bfloat162float(h));
        __syncthreads();
    }
}

// ---------------------------------------------------------------------------
extern "C" void kernel_launch(void* const* d_in, const int* in_sizes, int n_in,
                              void* d_out, int out_size)
{
    const float* in  = (const float*)d_in[0];
    const float* ew1 = (const float*)d_in[1];
    const float* eb1 = (const float*)d_in[2];
    const float* ew2 = (const float*)d_in[3];
    const float* eb2 = (const float*)d_in[4];
    const float* ew3 = (const float*)d_in[5];
    const float* eb3 = (const float*)d_in[6];
    const float* Aw  = (const float*)d_in[7];
    const float* Bw  = (const float*)d_in[8];
    const float* dw1 = (const float*)d_in[9];
    const float* db1 = (const float*)d_in[10];
    const float* dw2 = (const float*)d_in[11];
    const float* db2 = (const float*)d_in[12];
    const float* dw3 = (const float*)d_in[13];
    const float* db3 = (const float*)d_in[14];
    float* out = (float*)d_out;

    void *ph1, *ph2, *ph1e, *ph2e, *pz0;
    void *pazh, *pazl, *pw1h, *pw1l, *pw2h, *pw2l, *pw3h, *pw3l;
    void *puh, *pul, *pwlh, *pwll, *pwfh, *pwfl, *pch, *pcl;
    cudaGetSymbolAddress(&ph1, g_H1);
    cudaGetSymbolAddress(&ph2, g_H2);
    cudaGetSymbolAddress(&ph1e, g_h1e);
    cudaGetSymbolAddress(&ph2e, g_h2e);
    cudaGetSymbolAddress(&pz0, g_z0);
    cudaGetSymbolAddress(&pazh, g_AZh);
    cudaGetSymbolAddress(&pazl, g_AZl);
    cudaGetSymbolAddress(&pw1h, g_W1h);
    cudaGetSymbolAddress(&pw1l, g_W1l);
    cudaGetSymbolAddress(&pw2h, g_W2h);
    cudaGetSymbolAddress(&pw2l, g_W2l);
    cudaGetSymbolAddress(&pw3h, g_W3h);
    cudaGetSymbolAddress(&pw3l, g_W3l);
    cudaGetSymbolAddress(&puh, g_Uh);
    cudaGetSymbolAddress(&pul, g_Ul);
    cudaGetSymbolAddress(&pwlh, g_Wlh);
    cudaGetSymbolAddress(&pwll, g_Wll);
    cudaGetSymbolAddress(&pwfh, g_Wfh);
    cudaGetSymbolAddress(&pwfl, g_Wfl);
    cudaGetSymbolAddress(&pch, g_Ch);
    cudaGetSymbolAddress(&pcl, g_Cl);
    float* h1e = (float*)ph1e;
    float* h2e = (float*)ph2e;
    float* z0  = (float*)pz0;
    __nv_bfloat16* AZh = (__nv_bfloat16*)pazh;
    __nv_bfloat16* AZl = (__nv_bfloat16*)pazl;
    __nv_bfloat16* B1h = (__nv_bfloat16*)ph1;
    __nv_bfloat16* B1l = B1h + (size_t)NROWS * ENCD;
    __nv_bfloat16* B2h = (__nv_bfloat16*)ph2;
    __nv_bfloat16* B2l = B2h + (size_t)NROWS * ENCD;

    cudaFuncSetAttribute(mma_gemm<1, 0>, cudaFuncAttributeMaxDynamicSharedMemorySize, MMA_SMEM);
    cudaFuncSetAttribute(mma_gemm<0, 1>, cudaFuncAttributeMaxDynamicSharedMemorySize, MMA_SMEM);
    cudaFuncSetAttribute(mma_gemm<0, 2>, cudaFuncAttributeMaxDynamicSharedMemorySize, MMA_SMEM);
    cudaFuncSetAttribute(mma_gemm<0, 3>, cudaFuncAttributeMaxDynamicSharedMemorySize, MMA_SMEM);

    // streams/events created once, outside graph capture
    static cudaStream_t s1 = nullptr, s2 = nullptr;
    static cudaEvent_t eFork = nullptr, eU = nullptr, eEnc = nullptr,
                       eSide = nullptr, eLA = nullptr, eCar = nullptr;
    if (!s1) {
        cudaStreamCreateWithFlags(&s1, cudaStreamNonBlocking);
        cudaStreamCreateWithFlags(&s2, cudaStreamNonBlocking);
        cudaEventCreateWithFlags(&eFork, cudaEventDisableTiming);
        cudaEventCreateWithFlags(&eU, cudaEventDisableTiming);
        cudaEventCreateWithFlags(&eEnc, cudaEventDisableTiming);
        cudaEventCreateWithFlags(&eSide, cudaEventDisableTiming);
        cudaEventCreateWithFlags(&eLA, cudaEventDisableTiming);
        cudaEventCreateWithFlags(&eCar, cudaEventDisableTiming);
    }

    // ---- fork side stream ----
    cudaEventRecord(eFork, 0);
    cudaStreamWaitEvent(s1, eFork, 0);

    // side stream s1: gatherU -> encoder -> decoder weight splits
    gatherU<<<(2048 * 512) / 256, 256, 0, s1>>>(in);
    cudaEventRecord(eU, s1);
    gemm_m64<<<ENCD / 64, 256, 0, s1>>>(in, (long long)Tt * Din, ew1, eb1, h1e, ENCD, 256, 1);
    gemm_m64<<<ENCD / 64, 256, 0, s1>>>(h1e, ENCD, ew2, eb2, h2e, ENCD, ENCD, 1);
    gemm_m64<<<LAT / 64, 256, 0, s1>>>(h2e, ENCD, ew3, eb3, z0, LAT, ENCD, 1);
    cudaEventRecord(eEnc, s1);
    split_w<<<(256 * 512 + 255) / 256, 256, 0, s1>>>(dw1, 256, 512, (__nv_bfloat16*)pw1h, (__nv_bfloat16*)pw1l);
    split_w<<<(512 * 512 + 255) / 256, 256, 0, s1>>>(dw2, 512, 512, (__nv_bfloat16*)pw2h, (__nv_bfloat16*)pw2l);
    split_w<<<(512 * 256 + 255) / 256, 256, 0, s1>>>(dw3, 512, 256, (__nv_bfloat16*)pw3h, (__nv_bfloat16*)pw3l);
    cudaEventRecord(eSide, s1);

    // main stream: A powers -> scan operand builds
    powinit_kernel<<<256, 256>>>(Aw);
    for (int half = 1; half <= 16; half <<= 1)
        pow_gemm<<<dim3(4, 4, half), 256>>>(half);
    buildG<<<32, 256>>>(Bw);
    buildWfix<<<(8192 * 256) / 256, 256>>>();
    buildWlocal<<<(8192 * 512) / 256, 256>>>();

    // local scan GEMM part A: s=31 columns only (x blocks 62..63)
    cudaStreamWaitEvent(0, eU, 0);
    mma_gemm<0, 2><<<dim3(2, 16), 256, MMA_SMEM>>>(
        (__nv_bfloat16*)puh, (__nv_bfloat16*)pul,
        (__nv_bfloat16*)pwlh, (__nv_bfloat16*)pwll,
        nullptr, nullptr, nullptr, nullptr, 8192, 512, 62);
    cudaEventRecord(eLA, 0);

    // local scan GEMM part B: remaining columns (x blocks 0..61)
    mma_gemm<0, 2><<<dim3(62, 16), 256, MMA_SMEM>>>(
        (__nv_bfloat16*)puh, (__nv_bfloat16*)pul,
        (__nv_bfloat16*)pwlh, (__nv_bfloat16*)pwll,
        nullptr, nullptr, nullptr, nullptr, 8192, 512, 0);

    // carry chain on s2, overlapped with local part B
    cudaStreamWaitEvent(s2, eLA, 0);
    cudaStreamWaitEvent(s2, eEnc, 0);
    carry_chain64<<<64, 256, 0, s2>>>(z0);
    cudaEventRecord(eCar, s2);

    // fused fix GEMM: carry @ [A^1..A^32] + g_ZB -> AZ hi/lo bf16
    cudaStreamWaitEvent(0, eCar, 0);
    mma_gemm<0, 3><<<dim3(64, 16), 256, MMA_SMEM>>>(
        (__nv_bfloat16*)pch, (__nv_bfloat16*)pcl,
        (__nv_bfloat16*)pwfh, (__nv_bfloat16*)pwfl,
        nullptr, nullptr, nullptr, nullptr, 8192, 256, 0);

    // decoder needs weight splits -- full join here
    cudaStreamWaitEvent(0, eSide, 0);
    mma_gemm<1, 0><<<dim3(ENCD / 128, NROWS / 128), 256, MMA_SMEM>>>(
        AZh, AZl, (__nv_bfloat16*)pw1h, (__nv_bfloat16*)pw1l, db1,
        B1h, B1l, nullptr, ENCD, LAT, 0);
    mma_gemm<1, 0><<<dim3(ENCD / 128, NROWS / 128), 256, MMA_SMEM>>>(
        B1h, B1l, (__nv_bfloat16*)pw2h, (__nv_bfloat16*)pw2l, db2,
        B2h, B2l, nullptr, ENCD, ENCD, 0);
    mma_gemm<0, 1><<<dim3(LAT / 128, NROWS / 128), 256, MMA_SMEM>>>(
        B2h, B2l, (__nv_bfloat16*)pw3h, (__nv_bfloat16*)pw3l, db3,
        nullptr, nullptr, out, LAT, ENCD, 0);
}

// round 16
// speedup vs baseline: 1.1877x; 1.1877x over previous
#include <cuda_runtime.h>
#include <cuda_bf16.h>
#include <cuda_fp16.h>
#include <cstdint>

// ---------------------------------------------------------------------------
// HiroLRAN: encoder(t=0) -> rank-16 scan-as-GEMM (bf16 3-product) -> fix
// (fp32 z) -> dynamic-scale f16 convert -> decoder (f16 x split-f16 weights,
// 2 HMMA products, alpha-scaled). occ=2 on mma kernels. Dual-stream prologue.
// ---------------------------------------------------------------------------

#define Bsz 64
#define Tt 1024
#define Din 288
#define LAT 256
#define ENCD 512
#define NROWS (Bsz * Tt)   // 65536
#define PADK 40            // padded K-stride (elements): 80B rows

// scratch (device globals: no allocations allowed)
__device__ float g_ZB[(size_t)NROWS * LAT];
__device__ float g_H1[(size_t)NROWS * ENCD];     // aliased: H1 f16
__device__ float g_H2[(size_t)NROWS * ENCD];     // aliased: H2 f16
__device__ float g_Apow[33 * LAT * LAT];         // A^1..A^32 at idx 1..32
__device__ float g_h1e[Bsz * ENCD];
__device__ float g_h2e[Bsz * ENCD];
__device__ float g_z0[Bsz * LAT];
__device__ float g_G[32 * 16 * 256];             // G_r = B A^r
__device__ unsigned g_maxbits;                   // max |z| as float bits
__device__ float g_alpha[2];                     // {alpha, 1/alpha}
__device__ __half g_AZ16[(size_t)NROWS * LAT];   // alpha-scaled z, f16
__device__ __half g_W1h[ENCD * LAT], g_W1l[ENCD * LAT];   // N x K f16
__device__ __half g_W2h[ENCD * ENCD], g_W2l[ENCD * ENCD];
__device__ __half g_W3h[LAT * ENCD], g_W3l[LAT * ENCD];
__device__ __nv_bfloat16 g_Uh[2048 * 512], g_Ul[2048 * 512];     // gathered u
__device__ __nv_bfloat16 g_Wlh[8192 * 512], g_Wll[8192 * 512];   // Toeplitz G
__device__ __nv_bfloat16 g_Wfh[8192 * 256], g_Wfl[8192 * 256];   // [A^1..A^32]
__device__ __nv_bfloat16 g_Ch[2048 * 256], g_Cl[2048 * 256];     // split carry

// ---- async copy helpers -----------------------------------------------------
__device__ __forceinline__ uint32_t smem_u32(const void* p) {
    return (uint32_t)__cvta_generic_to_shared(p);
}
__device__ __forceinline__ void cpa16s(uint32_t saddr, const void* gsrc) {
    asm volatile("cp.async.ca.shared.global [%0], [%1], 16;\n" :: "r"(saddr), "l"(gsrc));
}
__device__ __forceinline__ void cpa_commit() {
    asm volatile("cp.async.commit_group;\n");
}
__device__ __forceinline__ void cpa_wait0() {
    asm volatile("cp.async.wait_group 0;\n" ::: "memory");
}
__device__ __forceinline__ void cpa_wait1() {
    asm volatile("cp.async.wait_group 1;\n" ::: "memory");
}

// ---- warp-level mma helpers ---------------------------------------------------
__device__ __forceinline__ void ldsm4(uint32_t addr, uint32_t& r0, uint32_t& r1,
                                      uint32_t& r2, uint32_t& r3) {
    asm volatile("ldmatrix.sync.aligned.m8n8.x4.shared.b16 {%0,%1,%2,%3}, [%4];"
                 : "=r"(r0), "=r"(r1), "=r"(r2), "=r"(r3) : "r"(addr));
}
__device__ __forceinline__ void mma_bf(float* c, const uint32_t* a,
                                       const uint32_t* b) {
    asm volatile(
        "mma.sync.aligned.m16n8k16.row.col.f32.bf16.bf16.f32 "
        "{%0,%1,%2,%3}, {%4,%5,%6,%7}, {%8,%9}, {%0,%1,%2,%3};"
        : "+f"(c[0]), "+f"(c[1]), "+f"(c[2]), "+f"(c[3])
        : "r"(a[0]), "r"(a[1]), "r"(a[2]), "r"(a[3]), "r"(b[0]), "r"(b[1]));
}
__device__ __forceinline__ void mma_f16(float* c, const uint32_t* a,
                                        const uint32_t* b) {
    asm volatile(
        "mma.sync.aligned.m16n8k16.row.col.f32.f16.f16.f32 "
        "{%0,%1,%2,%3}, {%4,%5,%6,%7}, {%8,%9}, {%0,%1,%2,%3};"
        : "+f"(c[0]), "+f"(c[1]), "+f"(c[2]), "+f"(c[3])
        : "r"(a[0]), "r"(a[1]), "r"(a[2]), "r"(a[3]), "r"(b[0]), "r"(b[1]));
}

// ---------------------------------------------------------------------------
// bf16 3-product scan GEMM (proven). 128x128 tile, 8 warps, BK=32. occ=2.
// OUT 2: scatter STORE fp32 -> g_ZB (local scan; triangular K-cut)
// OUT 3: scatter: read g_ZB, add carry product, write fp32 back (fused fix)
// ---------------------------------------------------------------------------
#define STAGE_ELEMS (4 * 128 * PADK)
#define MMA_SMEM (2 * STAGE_ELEMS * 2)   // 81920 B

template<int OUT>
__global__ __launch_bounds__(256, 2)
void mma_scan(const __nv_bfloat16* __restrict__ Ah, const __nv_bfloat16* __restrict__ Al,
              const __nv_bfloat16* __restrict__ Bh, const __nv_bfloat16* __restrict__ Bl,
              int N, int K)
{
    extern __shared__ __align__(16) __nv_bfloat16 smem[];
    const int tid  = threadIdx.x;
    const int warp = tid >> 5;
    const int lane = tid & 31;
    const int crow = blockIdx.y * 128;
    const int ccol = blockIdx.x * 128;
    const int mo = (warp >> 2) * 64;
    const int no = (warp & 3) * 32;

    const __nv_bfloat16* gsrc[4] = {
        Ah + (size_t)crow * K, Al + (size_t)crow * K,
        Bh + (size_t)ccol * K, Bl + (size_t)ccol * K };

    auto load_chunk = [&](int s, int kc) {
#pragma unroll
        for (int q = 0; q < 4; q++) {
            const __nv_bfloat16* src = gsrc[q] + kc * 32;
            __nv_bfloat16* dstb = smem + s * STAGE_ELEMS + q * 128 * PADK;
#pragma unroll
            for (int t = 0; t < 2; t++) {
                int g = tid + t * 256;
                int row = g >> 2, c = g & 3;
                cpa16s(smem_u32(dstb + row * PADK + c * 8),
                       src + (size_t)row * K + c * 8);
            }
        }
        cpa_commit();
    };

    float acc[4][4][4];
#pragma unroll
    for (int i = 0; i < 4; i++)
#pragma unroll
        for (int j = 0; j < 4; j++)
#pragma unroll
            for (int v = 0; v < 4; v++) acc[i][j][v] = 0.f;

    int Keff = K;
    if (OUT == 2) {
        int s = ccol >> 8;
        int kneed = 16 * (s + 1);
        Keff = (kneed + 31) & ~31;
        if (Keff > K) Keff = K;
    }
    const int nch = Keff / 32;

    load_chunk(0, 0);
    if (nch > 1) load_chunk(1, 1);

    const int a_rowsel = lane & 15;
    const int a_colsel = (lane >> 4) << 3;
    const int b_rowsel = ((lane >> 4) << 3) + (lane & 7);
    const int b_colsel = ((lane >> 3) & 1) << 3;

    for (int i = 0; i < nch; i++) {
        const int s = i & 1;
        if (i + 1 < nch) cpa_wait1(); else cpa_wait0();
        __syncthreads();
        const uint32_t stb = smem_u32(smem) + s * STAGE_ELEMS * 2;
        const uint32_t bAh = stb;
        const uint32_t bAl = stb + 128 * PADK * 2;
        const uint32_t bBh = stb + 2 * 128 * PADK * 2;
        const uint32_t bBl = stb + 3 * 128 * PADK * 2;
#pragma unroll
        for (int kk = 0; kk < 2; kk++) {
            const int kc = kk * 16;
            uint32_t a[4][4], b[4][2], bl[4][2];
#pragma unroll
            for (int it = 0; it < 4; it++) {
                int row = mo + it * 16 + a_rowsel;
                ldsm4(bAh + (row * PADK + kc + a_colsel) * 2,
                      a[it][0], a[it][1], a[it][2], a[it][3]);
            }
#pragma unroll
            for (int jj = 0; jj < 2; jj++) {
                int row = no + jj * 16 + b_rowsel;
                ldsm4(bBh + (row * PADK + kc + b_colsel) * 2,
                      b[2 * jj][0], b[2 * jj][1], b[2 * jj + 1][0], b[2 * jj + 1][1]);
            }
#pragma unroll
            for (int it = 0; it < 4; it++)
#pragma unroll
                for (int jt = 0; jt < 4; jt++) mma_bf(acc[it][jt], a[it], b[jt]);
#pragma unroll
            for (int jj = 0; jj < 2; jj++) {
                int row = no + jj * 16 + b_rowsel;
                ldsm4(bBl + (row * PADK + kc + b_colsel) * 2,
                      bl[2 * jj][0], bl[2 * jj][1], bl[2 * jj + 1][0], bl[2 * jj + 1][1]);
            }
#pragma unroll
            for (int it = 0; it < 4; it++)
#pragma unroll
                for (int jt = 0; jt < 4; jt++) mma_bf(acc[it][jt], a[it], bl[jt]);
#pragma unroll
            for (int it = 0; it < 4; it++) {
                int row = mo + it * 16 + a_rowsel;
                ldsm4(bAl + (row * PADK + kc + a_colsel) * 2,
                      a[it][0], a[it][1], a[it][2], a[it][3]);
            }
#pragma unroll
            for (int it = 0; it < 4; it++)
#pragma unroll
                for (int jt = 0; jt < 4; jt++) mma_bf(acc[it][jt], a[it], b[jt]);
        }
        __syncthreads();
        if (i + 2 < nch) load_chunk(s, i + 2);
    }

#pragma unroll
    for (int it = 0; it < 4; it++) {
#pragma unroll
        for (int jt = 0; jt < 4; jt++) {
            const int r0 = crow + mo + it * 16 + (lane >> 2);
            const int gc = ccol + no + jt * 8 + (lane & 3) * 2;
            float v00 = acc[it][jt][0], v01 = acc[it][jt][1];
            float v10 = acc[it][jt][2], v11 = acc[it][jt][3];
            const int s  = gc >> 8;
            const int j  = gc & 255;
            const int c  = r0 >> 6;
            const int b0 = r0 & 63;
            const int t  = c * 32 + s;
            size_t i0 = ((size_t)b0 * Tt + t) * 256 + j;
            size_t i1 = ((size_t)(b0 + 8) * Tt + t) * 256 + j;
            if (OUT == 2) {
                *reinterpret_cast<float2*>(&g_ZB[i0]) = make_float2(v00, v01);
                *reinterpret_cast<float2*>(&g_ZB[i1]) = make_float2(v10, v11);
            } else {
                float2 z0 = *reinterpret_cast<const float2*>(&g_ZB[i0]);
                float2 z1 = *reinterpret_cast<const float2*>(&g_ZB[i1]);
                z0.x += v00; z0.y += v01; z1.x += v10; z1.y += v11;
                *reinterpret_cast<float2*>(&g_ZB[i0]) = z0;
                *reinterpret_cast<float2*>(&g_ZB[i1]) = z1;
            }
        }
    }
}

// ---------------------------------------------------------------------------
// dynamic scale: max |z| -> alpha with alpha*max in [32,64)
// ---------------------------------------------------------------------------
__global__ void reduce_max_z()
{
    size_t i = ((size_t)blockIdx.x * 256 + threadIdx.x) * 4;
    float4 v = *reinterpret_cast<const float4*>(&g_ZB[i]);
    float m = fmaxf(fmaxf(fabsf(v.x), fabsf(v.y)), fmaxf(fabsf(v.z), fabsf(v.w)));
#pragma unroll
    for (int o = 16; o; o >>= 1) m = fmaxf(m, __shfl_xor_sync(~0u, m, o));
    __shared__ float wm[8];
    if ((threadIdx.x & 31) == 0) wm[threadIdx.x >> 5] = m;
    __syncthreads();
    if (threadIdx.x < 8) {
        m = wm[threadIdx.x];
#pragma unroll
        for (int o = 4; o; o >>= 1) m = fmaxf(m, __shfl_xor_sync(0xff, m, o));
        if (threadIdx.x == 0) atomicMax(&g_maxbits, __float_as_uint(m));
    }
}
__global__ void calc_alpha()
{
    float mx = __uint_as_float(g_maxbits);
    int e;
    frexpf(mx, &e);                 // mx = f * 2^e, f in [0.5, 1)
    float a = exp2f((float)(6 - e)); // a*mx in [32, 64)
    g_alpha[0] = a;
    g_alpha[1] = 1.f / a;
}
__global__ void conv_az()
{
    size_t i = ((size_t)blockIdx.x * 256 + threadIdx.x) * 4;
    float a = g_alpha[0];
    float4 v = *reinterpret_cast<const float4*>(&g_ZB[i]);
    *reinterpret_cast<__half2*>(&g_AZ16[i]) =
        __halves2half2(__float2half_rn(v.x * a), __float2half_rn(v.y * a));
    *reinterpret_cast<__half2*>(&g_AZ16[i + 2]) =
        __halves2half2(__float2half_rn(v.z * a), __float2half_rn(v.w * a));
}

// ---------------------------------------------------------------------------
// f16 2-product decoder GEMM: C = act(A16 @ (Wh+Wl)^T + alpha*bias) (scaled).
// OUTF 0: f16 hidden out (alpha-scaled); OUTF 1: fp32 out (unscaled, +bias).
// ---------------------------------------------------------------------------
#define DEC_TILE (128 * PADK * 2)      // 10240 B
#define DEC_STAGE (3 * DEC_TILE)       // 30720 B
#define DEC_SMEM (2 * DEC_STAGE)       // 61440 B

template<int ACT, int OUTF>
__global__ __launch_bounds__(256, 2)
void mma_dec(const __half* __restrict__ A, const __half* __restrict__ Wh,
             const __half* __restrict__ Wl, const float* __restrict__ bias,
             __half* __restrict__ oH, float* __restrict__ oF, int N, int K)
{
    extern __shared__ __align__(16) uint8_t smem8[];
    const int tid  = threadIdx.x;
    const int warp = tid >> 5;
    const int lane = tid & 31;
    const int crow = blockIdx.y * 128;
    const int ccol = blockIdx.x * 128;
    const int mo = (warp >> 2) * 64;
    const int no = (warp & 3) * 32;
    const float aSc  = g_alpha[0];
    const float iSc  = g_alpha[1];

    const __half* gsrc[3] = {
        A + (size_t)crow * K, Wh + (size_t)ccol * K, Wl + (size_t)ccol * K };

    auto load_chunk = [&](int s, int kc) {
        const uint32_t stb = smem_u32(smem8) + s * DEC_STAGE;
#pragma unroll
        for (int q = 0; q < 3; q++) {
            const __half* src = gsrc[q] + kc * 32;
            const uint32_t tb = stb + q * DEC_TILE;
#pragma unroll
            for (int t = 0; t < 2; t++) {
                int g = tid + t * 256;
                int row = g >> 2, c = g & 3;
                cpa16s(tb + row * 80 + c * 16, src + (size_t)row * K + c * 8);
            }
        }
        cpa_commit();
    };

    float acc[4][4][4];
#pragma unroll
    for (int i = 0; i < 4; i++)
#pragma unroll
        for (int j = 0; j < 4; j++)
#pragma unroll
            for (int v = 0; v < 4; v++) acc[i][j][v] = 0.f;

    const int nch = K / 32;
    load_chunk(0, 0);
    load_chunk(1, 1);

    const int a_rowsel = lane & 15;
    const int a_colsel = (lane >> 4) << 3;
    const int b_rowsel = ((lane >> 4) << 3) + (lane & 7);
    const int b_colsel = ((lane >> 3) & 1) << 3;

    for (int i = 0; i < nch; i++) {
        const int s = i & 1;
        if (i + 1 < nch) cpa_wait1(); else cpa_wait0();
        __syncthreads();
        const uint32_t stb = smem_u32(smem8) + s * DEC_STAGE;
        const uint32_t tA  = stb;
        const uint32_t tWh = stb + DEC_TILE;
        const uint32_t tWl = stb + 2 * DEC_TILE;
#pragma unroll
        for (int kk = 0; kk < 2; kk++) {
            const int kc = kk * 16;
            uint32_t a[4][4], b[4][2];
#pragma unroll
            for (int it = 0; it < 4; it++) {
                int row = mo + it * 16 + a_rowsel;
                ldsm4(tA + row * 80 + (kc + a_colsel) * 2,
                      a[it][0], a[it][1], a[it][2], a[it][3]);
            }
#pragma unroll
            for (int jj = 0; jj < 2; jj++) {
                int row = no + jj * 16 + b_rowsel;
                ldsm4(tWh + row * 80 + (kc + b_colsel) * 2,
                      b[2 * jj][0], b[2 * jj][1], b[2 * jj + 1][0], b[2 * jj + 1][1]);
            }
#pragma unroll
            for (int it = 0; it < 4; it++)
#pragma unroll
                for (int jt = 0; jt < 4; jt++) mma_f16(acc[it][jt], a[it], b[jt]);
#pragma unroll
            for (int jj = 0; jj < 2; jj++) {
                int row = no + jj * 16 + b_rowsel;
                ldsm4(tWl + row * 80 + (kc + b_colsel) * 2,
                      b[2 * jj][0], b[2 * jj][1], b[2 * jj + 1][0], b[2 * jj + 1][1]);
            }
#pragma unroll
            for (int it = 0; it < 4; it++)
#pragma unroll
                for (int jt = 0; jt < 4; jt++) mma_f16(acc[it][jt], a[it], b[jt]);
        }
        __syncthreads();
        if (i + 2 < nch) load_chunk(s, i + 2);
    }

#pragma unroll
    for (int it = 0; it < 4; it++) {
#pragma unroll
        for (int jt = 0; jt < 4; jt++) {
            const int r0 = crow + mo + it * 16 + (lane >> 2);
            const int gc = ccol + no + jt * 8 + (lane & 3) * 2;
            if (OUTF == 0) {
                const float b0 = bias[gc] * aSc, b1 = bias[gc + 1] * aSc;
                float v00 = acc[it][jt][0] + b0, v01 = acc[it][jt][1] + b1;
                float v10 = acc[it][jt][2] + b0, v11 = acc[it][jt][3] + b1;
                if (ACT) {
                    v00 = (v00 >= 0.f) ? v00 : 0.01f * v00;
                    v01 = (v01 >= 0.f) ? v01 : 0.01f * v01;
                    v10 = (v10 >= 0.f) ? v10 : 0.01f * v10;
                    v11 = (v11 >= 0.f) ? v11 : 0.01f * v11;
                }
                *reinterpret_cast<__half2*>(oH + (size_t)r0 * N + gc) =
                    __halves2half2(__float2half_rn(v00), __float2half_rn(v01));
                *reinterpret_cast<__half2*>(oH + (size_t)(r0 + 8) * N + gc) =
                    __halves2half2(__float2half_rn(v10), __float2half_rn(v11));
            } else {
                const float b0 = bias[gc], b1 = bias[gc + 1];
                float v00 = acc[it][jt][0] * iSc + b0, v01 = acc[it][jt][1] * iSc + b1;
                float v10 = acc[it][jt][2] * iSc + b0, v11 = acc[it][jt][3] * iSc + b1;
                *reinterpret_cast<float2*>(oF + (size_t)r0 * N + gc) = make_float2(v00, v01);
                *reinterpret_cast<float2*>(oF + (size_t)(r0 + 8) * N + gc) = make_float2(v10, v11);
            }
        }
    }
}

// decoder weights: W (K x N fp32) -> Wh/Wl (N x K f16)
__global__ void conv_w16(const float* __restrict__ W, int K, int N,
                         __half* __restrict__ wh, __half* __restrict__ wl)
{
    int idx = blockIdx.x * 256 + threadIdx.x;
    if (idx >= K * N) return;
    int k = idx / N, n = idx % N;
    float v = W[idx];
    __half h = __float2half_rn(v);
    wh[(size_t)n * K + k] = h;
    wl[(size_t)n * K + k] = __float2half_rn(v - __half2float(h));
}

// gather u slices -> U[2048 x 512] split bf16
__global__ void gatherU(const float* __restrict__ in)
{
    int idx = blockIdx.x * 256 + threadIdx.x;
    if (idx >= 2048 * 512) return;
    int m = idx >> 9, k = idx & 511;
    int c = m >> 6, b = m & 63;
    int j = k >> 4, i = k & 15;
    float v = in[((size_t)b * Tt + c * 32 + j) * Din + 272 + i];
    __nv_bfloat16 h = __float2bfloat16(v);
    g_Uh[idx] = h;
    g_Ul[idx] = __float2bfloat16(v - __bfloat162float(h));
}

// G_r = B_w @ A^r (r=0..31)
__global__ void buildG(const float* __restrict__ Bw)
{
    const int r = blockIdx.x;
    const int n = threadIdx.x;
    if (r == 0) {
        for (int i = 0; i < 16; i++)
            g_G[i * 256 + n] = Bw[i * 256 + n];
        return;
    }
    const float* Ar = g_Apow + (size_t)r * 65536;
    float acc[16];
#pragma unroll
    for (int i = 0; i < 16; i++) acc[i] = 0.f;
    for (int m = 0; m < 256; m++) {
        float a = Ar[m * 256 + n];
#pragma unroll
        for (int i = 0; i < 16; i++)
            acc[i] = fmaf(Bw[i * 256 + m], a, acc[i]);
    }
#pragma unroll
    for (int i = 0; i < 16; i++)
        g_G[(r * 16 + i) * 256 + n] = acc[i];
}

__global__ void buildWlocal()
{
    int idx = blockIdx.x * 256 + threadIdx.x;
    if (idx >= 8192 * 512) return;
    int n = idx >> 9, k = idx & 511;
    int s = n >> 8, col = n & 255, j = k >> 4, i = k & 15;
    int r = s - j;
    float v = (r >= 0) ? g_G[(r * 16 + i) * 256 + col] : 0.f;
    __nv_bfloat16 h = __float2bfloat16(v);
    g_Wlh[idx] = h;
    g_Wll[idx] = __float2bfloat16(v - __bfloat162float(h));
}

__global__ void buildWfix()
{
    int idx = blockIdx.x * 256 + threadIdx.x;
    if (idx >= 8192 * 256) return;
    int n = idx >> 8, k = idx & 255;
    int s = n >> 8, col = n & 255;
    float v = g_Apow[(size_t)(s + 1) * 65536 + k * 256 + col];
    __nv_bfloat16 h = __float2bfloat16(v);
    g_Wfh[idx] = h;
    g_Wfl[idx] = __float2bfloat16(v - __bfloat162float(h));
}

// ---------------------------------------------------------------------------
// Small-M GEMM (encoder, M=64)
// ---------------------------------------------------------------------------
__global__ __launch_bounds__(256)
void gemm_m64(const float* __restrict__ A, long long lda,
              const float* __restrict__ W,
              const float* __restrict__ bias,
              float* __restrict__ C,
              int N, int K, int act)
{
    __shared__ __align__(16) float As[2][16][64];
    __shared__ __align__(16) float Ws[2][16][64];
    const int tid  = threadIdx.x;
    const int ccol = blockIdx.x * 64;
    const int ar = tid >> 2, ak = (tid & 3) * 4;
    const int wr = tid >> 4, wc = (tid & 15) * 4;
    const int ty = tid >> 4, tx = tid & 15;
    float acc[4][4] = {};

    float4 av = *reinterpret_cast<const float4*>(A + (size_t)ar * lda + ak);
    float4 wv = *reinterpret_cast<const float4*>(W + (size_t)wr * N + ccol + wc);
    As[0][ak + 0][ar] = av.x; As[0][ak + 1][ar] = av.y;
    As[0][ak + 2][ar] = av.z; As[0][ak + 3][ar] = av.w;
    *reinterpret_cast<float4*>(&Ws[0][wr][wc]) = wv;
    __syncthreads();

    int buf = 0;
    for (int k0 = 0; k0 < K; k0 += 16) {
        const bool next = (k0 + 16) < K;
        if (next) {
            av = *reinterpret_cast<const float4*>(A + (size_t)ar * lda + k0 + 16 + ak);
            wv = *reinterpret_cast<const float4*>(W + (size_t)(k0 + 16 + wr) * N + ccol + wc);
        }
#pragma unroll
        for (int k = 0; k < 16; k++) {
            float4 a4 = *reinterpret_cast<const float4*>(&As[buf][k][ty * 4]);
            float4 w4 = *reinterpret_cast<const float4*>(&Ws[buf][k][tx * 4]);
            float ar_[4] = {a4.x, a4.y, a4.z, a4.w};
            float wr_[4] = {w4.x, w4.y, w4.z, w4.w};
#pragma unroll
            for (int i = 0; i < 4; i++)
#pragma unroll
                for (int j = 0; j < 4; j++)
                    acc[i][j] = fmaf(ar_[i], wr_[j], acc[i][j]);
        }
        if (next) {
            As[buf ^ 1][ak + 0][ar] = av.x; As[buf ^ 1][ak + 1][ar] = av.y;
            As[buf ^ 1][ak + 2][ar] = av.z; As[buf ^ 1][ak + 3][ar] = av.w;
            *reinterpret_cast<float4*>(&Ws[buf ^ 1][wr][wc]) = wv;
        }
        __syncthreads();
        buf ^= 1;
    }
    float b4[4];
#pragma unroll
    for (int j = 0; j < 4; j++) b4[j] = bias[ccol + tx * 4 + j];
#pragma unroll
    for (int i = 0; i < 4; i++) {
        float o[4];
#pragma unroll
        for (int j = 0; j < 4; j++) {
            float v = acc[i][j] + b4[j];
            if (act) v = (v >= 0.f) ? v : 0.01f * v;
            o[j] = v;
        }
        *reinterpret_cast<float4*>(C + (size_t)(ty * 4 + i) * N + ccol + tx * 4) =
            make_float4(o[0], o[1], o[2], o[3]);
    }
}

__global__ void powinit_kernel(const float* __restrict__ A)
{
    const int i = blockIdx.x * 256 + threadIdx.x;
    g_Apow[65536 + i] = A[i];
    if (blockIdx.x == 0 && threadIdx.x == 0) g_maxbits = 0u;
}

// Apow[half+q] = Apow[half] @ Apow[q]; register-double-buffered loads
__global__ __launch_bounds__(256)
void pow_gemm(int half)
{
    const int q = blockIdx.z + 1;
    const float* S1 = g_Apow + (size_t)half * 65536;
    const float* S2 = g_Apow + (size_t)q * 65536;
    float* D = g_Apow + (size_t)(half + q) * 65536;
    const int ib = blockIdx.y * 64, jb = blockIdx.x * 64;
    __shared__ __align__(16) float As[2][16][64];
    __shared__ __align__(16) float Bs[2][16][64];
    const int tid = threadIdx.x;
    const int ar = tid >> 2, ak = (tid & 3) * 4;
    const int wr = tid >> 4, wc = (tid & 15) * 4;
    const int ty = tid >> 4, tx = tid & 15;
    float acc[4][4] = {};

    float4 av = *reinterpret_cast<const float4*>(S1 + (size_t)(ib + ar) * 256 + ak);
    float4 wv = *reinterpret_cast<const float4*>(S2 + (size_t)wr * 256 + jb + wc);
    As[0][ak + 0][ar] = av.x; As[0][ak + 1][ar] = av.y;
    As[0][ak + 2][ar] = av.z; As[0][ak + 3][ar] = av.w;
    *reinterpret_cast<float4*>(&Bs[0][wr][wc]) = wv;
    __syncthreads();

    int buf = 0;
    for (int k0 = 0; k0 < 256; k0 += 16) {
        const bool next = (k0 + 16) < 256;
        if (next) {
            av = *reinterpret_cast<const float4*>(S1 + (size_t)(ib + ar) * 256 + k0 + 16 + ak);
            wv = *reinterpret_cast<const float4*>(S2 + (size_t)(k0 + 16 + wr) * 256 + jb + wc);
        }
#pragma unroll
        for (int k = 0; k < 16; k++) {
            float4 a4 = *reinterpret_cast<const float4*>(&As[buf][k][ty * 4]);
            float4 w4 = *reinterpret_cast<const float4*>(&Bs[buf][k][tx * 4]);
            float ar_[4] = {a4.x, a4.y, a4.z, a4.w};
            float wr_[4] = {w4.x, w4.y, w4.z, w4.w};
#pragma unroll
            for (int i = 0; i < 4; i++)
#pragma unroll
                for (int j = 0; j < 4; j++)
                    acc[i][j] = fmaf(ar_[i], wr_[j], acc[i][j]);
        }
        if (next) {
            As[buf ^ 1][ak + 0][ar] = av.x; As[buf ^ 1][ak + 1][ar] = av.y;
            As[buf ^ 1][ak + 2][ar] = av.z; As[buf ^ 1][ak + 3][ar] = av.w;
            *reinterpret_cast<float4*>(&Bs[buf ^ 1][wr][wc]) = wv;
        }
        __syncthreads();
        buf ^= 1;
    }
#pragma unroll
    for (int i = 0; i < 4; i++)
        *reinterpret_cast<float4*>(D + (size_t)(ib + ty * 4 + i) * 256 + jb + tx * 4) =
            make_float4(acc[i][0], acc[i][1], acc[i][2], acc[i][3]);
}

// carry chain: 64 blocks, 4-way accumulators, unroll 4, fused bf16 split out
__global__ void carry_chain64(const float* __restrict__ z0)
{
    const int b = blockIdx.x;
    const int j = threadIdx.x;
    __shared__ float cp[256];
    float cur = z0[b * 256 + j];
    cp[j] = cur;
    {
        __nv_bfloat16 h = __float2bfloat16(cur);
        g_Ch[(size_t)b * 256 + j] = h;
        g_Cl[(size_t)b * 256 + j] = __float2bfloat16(cur - __bfloat162float(h));
    }
    __syncthreads();
    const float* A32 = g_Apow + (size_t)32 * 65536;
    for (int c = 1; c < 32; c++) {
        float s0 = g_ZB[((size_t)b * Tt + c * 32 - 1) * 256 + j];
        float s1 = 0.f, s2 = 0.f, s3 = 0.f;
#pragma unroll 4
        for (int k = 0; k < 256; k += 4) {
            s0 = fmaf(cp[k + 0], A32[(size_t)(k + 0) * 256 + j], s0);
            s1 = fmaf(cp[k + 1], A32[(size_t)(k + 1) * 256 + j], s1);
            s2 = fmaf(cp[k + 2], A32[(size_t)(k + 2) * 256 + j], s2);
            s3 = fmaf(cp[k + 3], A32[(size_t)(k + 3) * 256 + j], s3);
        }
        float a = (s0 + s1) + (s2 + s3);
        __syncthreads();
        cp[j] = a;
        __nv_bfloat16 h = __float2bfloat16(a);
        g_Ch[((size_t)c * 64 + b) * 256 + j] = h;
        g_Cl[((size_t)c * 64 + b) * 256 + j] = __float2bfloat16(a - __bfloat162float(h));
        __syncthreads();
    }
}

// ---------------------------------------------------------------------------
extern "C" void kernel_launch(void* const* d_in, const int* in_sizes, int n_in,
                              void* d_out, int out_size)
{
    const float* in  = (const float*)d_in[0];
    const float* ew1 = (const float*)d_in[1];
    const float* eb1 = (const float*)d_in[2];
    const float* ew2 = (const float*)d_in[3];
    const float* eb2 = (const float*)d_in[4];
    const float* ew3 = (const float*)d_in[5];
    const float* eb3 = (const float*)d_in[6];
    const float* Aw  = (const float*)d_in[7];
    const float* Bw  = (const float*)d_in[8];
    const float* dw1 = (const float*)d_in[9];
    const float* db1 = (const float*)d_in[10];
    const float* dw2 = (const float*)d_in[11];
    const float* db2 = (const float*)d_in[12];
    const float* dw3 = (const float*)d_in[13];
    const float* db3 = (const float*)d_in[14];
    float* out = (float*)d_out;

    void *ph1, *ph2, *ph1e, *ph2e, *pz0, *paz;
    void *pw1h, *pw1l, *pw2h, *pw2l, *pw3h, *pw3l;
    void *puh, *pul, *pwlh, *pwll, *pwfh, *pwfl, *pch, *pcl;
    cudaGetSymbolAddress(&ph1, g_H1);
    cudaGetSymbolAddress(&ph2, g_H2);
    cudaGetSymbolAddress(&ph1e, g_h1e);
    cudaGetSymbolAddress(&ph2e, g_h2e);
    cudaGetSymbolAddress(&pz0, g_z0);
    cudaGetSymbolAddress(&paz, g_AZ16);
    cudaGetSymbolAddress(&pw1h, g_W1h);
    cudaGetSymbolAddress(&pw1l, g_W1l);
    cudaGetSymbolAddress(&pw2h, g_W2h);
    cudaGetSymbolAddress(&pw2l, g_W2l);
    cudaGetSymbolAddress(&pw3h, g_W3h);
    cudaGetSymbolAddress(&pw3l, g_W3l);
    cudaGetSymbolAddress(&puh, g_Uh);
    cudaGetSymbolAddress(&pul, g_Ul);
    cudaGetSymbolAddress(&pwlh, g_Wlh);
    cudaGetSymbolAddress(&pwll, g_Wll);
    cudaGetSymbolAddress(&pwfh, g_Wfh);
    cudaGetSymbolAddress(&pwfl, g_Wfl);
    cudaGetSymbolAddress(&pch, g_Ch);
    cudaGetSymbolAddress(&pcl, g_Cl);
    float* h1e = (float*)ph1e;
    float* h2e = (float*)ph2e;
    float* z0  = (float*)pz0;
    __half* AZ = (__half*)paz;
    __half* H1 = (__half*)ph1;
    __half* H2 = (__half*)ph2;

    cudaFuncSetAttribute(mma_scan<2>, cudaFuncAttributeMaxDynamicSharedMemorySize, MMA_SMEM);
    cudaFuncSetAttribute(mma_scan<3>, cudaFuncAttributeMaxDynamicSharedMemorySize, MMA_SMEM);
    cudaFuncSetAttribute(mma_dec<1, 0>, cudaFuncAttributeMaxDynamicSharedMemorySize, DEC_SMEM);
    cudaFuncSetAttribute(mma_dec<0, 1>, cudaFuncAttributeMaxDynamicSharedMemorySize, DEC_SMEM);

    // streams/events created once, outside graph capture
    static cudaStream_t s1 = nullptr;
    static cudaEvent_t eFork = nullptr, eU = nullptr, eEnc = nullptr, eSide = nullptr;
    if (!s1) {
        cudaStreamCreateWithFlags(&s1, cudaStreamNonBlocking);
        cudaEventCreateWithFlags(&eFork, cudaEventDisableTiming);
        cudaEventCreateWithFlags(&eU, cudaEventDisableTiming);
        cudaEventCreateWithFlags(&eEnc, cudaEventDisableTiming);
        cudaEventCreateWithFlags(&eSide, cudaEventDisableTiming);
    }

    // ---- fork side stream ----
    cudaEventRecord(eFork, 0);
    cudaStreamWaitEvent(s1, eFork, 0);

    // side stream: gatherU -> encoder -> decoder weight conversions
    gatherU<<<(2048 * 512) / 256, 256, 0, s1>>>(in);
    cudaEventRecord(eU, s1);
    gemm_m64<<<ENCD / 64, 256, 0, s1>>>(in, (long long)Tt * Din, ew1, eb1, h1e, ENCD, 256, 1);
    gemm_m64<<<ENCD / 64, 256, 0, s1>>>(h1e, ENCD, ew2, eb2, h2e, ENCD, ENCD, 1);
    gemm_m64<<<LAT / 64, 256, 0, s1>>>(h2e, ENCD, ew3, eb3, z0, LAT, ENCD, 1);
    cudaEventRecord(eEnc, s1);
    conv_w16<<<(256 * 512 + 255) / 256, 256, 0, s1>>>(dw1, 256, 512, (__half*)pw1h, (__half*)pw1l);
    conv_w16<<<(512 * 512 + 255) / 256, 256, 0, s1>>>(dw2, 512, 512, (__half*)pw2h, (__half*)pw2l);
    conv_w16<<<(512 * 256 + 255) / 256, 256, 0, s1>>>(dw3, 512, 256, (__half*)pw3h, (__half*)pw3l);
    cudaEventRecord(eSide, s1);

    // main stream: A powers -> scan operand builds
    powinit_kernel<<<256, 256>>>(Aw);
    for (int half = 1; half <= 16; half <<= 1)
        pow_gemm<<<dim3(4, 4, half), 256>>>(half);
    buildG<<<32, 256>>>(Bw);
    buildWfix<<<(8192 * 256) / 256, 256>>>();
    buildWlocal<<<(8192 * 512) / 256, 256>>>();

    // chunk-local scan as ONE GEMM (triangular K-cut) -> g_ZB
    cudaStreamWaitEvent(0, eU, 0);
    mma_scan<2><<<dim3(64, 16), 256, MMA_SMEM>>>(
        (__nv_bfloat16*)puh, (__nv_bfloat16*)pul,
        (__nv_bfloat16*)pwlh, (__nv_bfloat16*)pwll, 8192, 512);

    // carry chain (fused bf16 split out)
    cudaStreamWaitEvent(0, eEnc, 0);
    carry_chain64<<<64, 256>>>(z0);

    // fused fix GEMM: carry @ [A^1..A^32] + g_ZB -> fp32 z in g_ZB
    mma_scan<3><<<dim3(64, 16), 256, MMA_SMEM>>>(
        (__nv_bfloat16*)pch, (__nv_bfloat16*)pcl,
        (__nv_bfloat16*)pwfh, (__nv_bfloat16*)pwfl, 8192, 256);

    // dynamic scale: max |z| -> alpha -> f16 convert
    reduce_max_z<<<16384, 256>>>();
    calc_alpha<<<1, 1>>>();
    conv_az<<<16384, 256>>>();

    // decoder (f16 2-product, alpha-scaled)
    cudaStreamWaitEvent(0, eSide, 0);
    mma_dec<1, 0><<<dim3(ENCD / 128, NROWS / 128), 256, DEC_SMEM>>>(
        AZ, (__half*)pw1h, (__half*)pw1l, db1, H1, nullptr, ENCD, LAT);
    mma_dec<1, 0><<<dim3(ENCD / 128, NROWS / 128), 256, DEC_SMEM>>>(
        H1, (__half*)pw2h, (__half*)pw2l, db2, H2, nullptr, ENCD, ENCD);
    mma_dec<0, 1><<<dim3(LAT / 128, NROWS / 128), 256, DEC_SMEM>>>(
        H2, (__half*)pw3h, (__half*)pw3l, db3, nullptr, out, LAT, ENCD);
}

// round 17
// speedup vs baseline: 1.2437x; 1.0471x over previous
#include <cuda_runtime.h>
#include <cuda_bf16.h>
#include <cuda_fp16.h>
#include <cstdint>

// ---------------------------------------------------------------------------
// HiroLRAN R17: local scan GEMM -> f16 2-product (U f16, Wlocal split-f16);
// fix stays bf16 3-product with fused max-|z| reduce; decoder f16 2-product
// alpha-scaled. occ=2 on mma kernels. Dual-stream prologue.
// ---------------------------------------------------------------------------

#define Bsz 64
#define Tt 1024
#define Din 288
#define LAT 256
#define ENCD 512
#define NROWS (Bsz * Tt)   // 65536
#define PADK 40            // padded K-stride (elements): 80B rows

// scratch (device globals: no allocations allowed)
__device__ float g_ZB[(size_t)NROWS * LAT];
__device__ float g_H1[(size_t)NROWS * ENCD];     // aliased: H1 f16
__device__ float g_H2[(size_t)NROWS * ENCD];     // aliased: H2 f16
__device__ float g_Apow[33 * LAT * LAT];         // A^1..A^32 at idx 1..32
__device__ float g_h1e[Bsz * ENCD];
__device__ float g_h2e[Bsz * ENCD];
__device__ float g_z0[Bsz * LAT];
__device__ float g_G[32 * 16 * 256];             // G_r = B A^r
__device__ unsigned g_maxbits;                   // max |z| as float bits
__device__ float g_alpha[2];                     // {alpha, 1/alpha}
__device__ __half g_AZ16[(size_t)NROWS * LAT];   // alpha-scaled z, f16
__device__ __half g_W1h[ENCD * LAT], g_W1l[ENCD * LAT];   // N x K f16
__device__ __half g_W2h[ENCD * ENCD], g_W2l[ENCD * ENCD];
__device__ __half g_W3h[LAT * ENCD], g_W3l[LAT * ENCD];
__device__ __half g_Uf[2048 * 512];                        // gathered u, f16
__device__ __half g_Wlh16[8192 * 512], g_Wll16[8192 * 512]; // Toeplitz G f16
__device__ __nv_bfloat16 g_Wfh[8192 * 256], g_Wfl[8192 * 256];   // [A^1..A^32]
__device__ __nv_bfloat16 g_Ch[2048 * 256], g_Cl[2048 * 256];     // split carry

// ---- async copy helpers -----------------------------------------------------
__device__ __forceinline__ uint32_t smem_u32(const void* p) {
    return (uint32_t)__cvta_generic_to_shared(p);
}
__device__ __forceinline__ void cpa16s(uint32_t saddr, const void* gsrc) {
    asm volatile("cp.async.ca.shared.global [%0], [%1], 16;\n" :: "r"(saddr), "l"(gsrc));
}
__device__ __forceinline__ void cpa_commit() {
    asm volatile("cp.async.commit_group;\n");
}
__device__ __forceinline__ void cpa_wait0() {
    asm volatile("cp.async.wait_group 0;\n" ::: "memory");
}
__device__ __forceinline__ void cpa_wait1() {
    asm volatile("cp.async.wait_group 1;\n" ::: "memory");
}

// ---- warp-level mma helpers ---------------------------------------------------
__device__ __forceinline__ void ldsm4(uint32_t addr, uint32_t& r0, uint32_t& r1,
                                      uint32_t& r2, uint32_t& r3) {
    asm volatile("ldmatrix.sync.aligned.m8n8.x4.shared.b16 {%0,%1,%2,%3}, [%4];"
                 : "=r"(r0), "=r"(r1), "=r"(r2), "=r"(r3) : "r"(addr));
}
__device__ __forceinline__ void mma_bf(float* c, const uint32_t* a,
                                       const uint32_t* b) {
    asm volatile(
        "mma.sync.aligned.m16n8k16.row.col.f32.bf16.bf16.f32 "
        "{%0,%1,%2,%3}, {%4,%5,%6,%7}, {%8,%9}, {%0,%1,%2,%3};"
        : "+f"(c[0]), "+f"(c[1]), "+f"(c[2]), "+f"(c[3])
        : "r"(a[0]), "r"(a[1]), "r"(a[2]), "r"(a[3]), "r"(b[0]), "r"(b[1]));
}
__device__ __forceinline__ void mma_f16(float* c, const uint32_t* a,
                                        const uint32_t* b) {
    asm volatile(
        "mma.sync.aligned.m16n8k16.row.col.f32.f16.f16.f32 "
        "{%0,%1,%2,%3}, {%4,%5,%6,%7}, {%8,%9}, {%0,%1,%2,%3};"
        : "+f"(c[0]), "+f"(c[1]), "+f"(c[2]), "+f"(c[3])
        : "r"(a[0]), "r"(a[1]), "r"(a[2]), "r"(a[3]), "r"(b[0]), "r"(b[1]));
}

// ---------------------------------------------------------------------------
// bf16 3-product fix GEMM (proven). 128x128 tile, 8 warps, BK=32. occ=2.
// Scatter: read g_ZB, add carry product, write fp32 back; fused block
// max-|z| -> atomicMax(g_maxbits).
// ---------------------------------------------------------------------------
#define STAGE_ELEMS (4 * 128 * PADK)
#define MMA_SMEM (2 * STAGE_ELEMS * 2)   // 81920 B

__global__ __launch_bounds__(256, 2)
void mma_fix(const __nv_bfloat16* __restrict__ Ah, const __nv_bfloat16* __restrict__ Al,
             const __nv_bfloat16* __restrict__ Bh, const __nv_bfloat16* __restrict__ Bl,
             int N, int K)
{
    extern __shared__ __align__(16) __nv_bfloat16 smem[];
    const int tid  = threadIdx.x;
    const int warp = tid >> 5;
    const int lane = tid & 31;
    const int crow = blockIdx.y * 128;
    const int ccol = blockIdx.x * 128;
    const int mo = (warp >> 2) * 64;
    const int no = (warp & 3) * 32;

    const __nv_bfloat16* gsrc[4] = {
        Ah + (size_t)crow * K, Al + (size_t)crow * K,
        Bh + (size_t)ccol * K, Bl + (size_t)ccol * K };

    auto load_chunk = [&](int s, int kc) {
#pragma unroll
        for (int q = 0; q < 4; q++) {
            const __nv_bfloat16* src = gsrc[q] + kc * 32;
            __nv_bfloat16* dstb = smem + s * STAGE_ELEMS + q * 128 * PADK;
#pragma unroll
            for (int t = 0; t < 2; t++) {
                int g = tid + t * 256;
                int row = g >> 2, c = g & 3;
                cpa16s(smem_u32(dstb + row * PADK + c * 8),
                       src + (size_t)row * K + c * 8);
            }
        }
        cpa_commit();
    };

    float acc[4][4][4];
#pragma unroll
    for (int i = 0; i < 4; i++)
#pragma unroll
        for (int j = 0; j < 4; j++)
#pragma unroll
            for (int v = 0; v < 4; v++) acc[i][j][v] = 0.f;

    const int nch = K / 32;
    load_chunk(0, 0);
    load_chunk(1, 1);

    const int a_rowsel = lane & 15;
    const int a_colsel = (lane >> 4) << 3;
    const int b_rowsel = ((lane >> 4) << 3) + (lane & 7);
    const int b_colsel = ((lane >> 3) & 1) << 3;

    for (int i = 0; i < nch; i++) {
        const int s = i & 1;
        if (i + 1 < nch) cpa_wait1(); else cpa_wait0();
        __syncthreads();
        const uint32_t stb = smem_u32(smem) + s * STAGE_ELEMS * 2;
        const uint32_t bAh = stb;
        const uint32_t bAl = stb + 128 * PADK * 2;
        const uint32_t bBh = stb + 2 * 128 * PADK * 2;
        const uint32_t bBl = stb + 3 * 128 * PADK * 2;
#pragma unroll
        for (int kk = 0; kk < 2; kk++) {
            const int kc = kk * 16;
            uint32_t a[4][4], b[4][2], bl[4][2];
#pragma unroll
            for (int it = 0; it < 4; it++) {
                int row = mo + it * 16 + a_rowsel;
                ldsm4(bAh + (row * PADK + kc + a_colsel) * 2,
                      a[it][0], a[it][1], a[it][2], a[it][3]);
            }
#pragma unroll
            for (int jj = 0; jj < 2; jj++) {
                int row = no + jj * 16 + b_rowsel;
                ldsm4(bBh + (row * PADK + kc + b_colsel) * 2,
                      b[2 * jj][0], b[2 * jj][1], b[2 * jj + 1][0], b[2 * jj + 1][1]);
            }
#pragma unroll
            for (int it = 0; it < 4; it++)
#pragma unroll
                for (int jt = 0; jt < 4; jt++) mma_bf(acc[it][jt], a[it], b[jt]);
#pragma unroll
            for (int jj = 0; jj < 2; jj++) {
                int row = no + jj * 16 + b_rowsel;
                ldsm4(bBl + (row * PADK + kc + b_colsel) * 2,
                      bl[2 * jj][0], bl[2 * jj][1], bl[2 * jj + 1][0], bl[2 * jj + 1][1]);
            }
#pragma unroll
            for (int it = 0; it < 4; it++)
#pragma unroll
                for (int jt = 0; jt < 4; jt++) mma_bf(acc[it][jt], a[it], bl[jt]);
#pragma unroll
            for (int it = 0; it < 4; it++) {
                int row = mo + it * 16 + a_rowsel;
                ldsm4(bAl + (row * PADK + kc + a_colsel) * 2,
                      a[it][0], a[it][1], a[it][2], a[it][3]);
            }
#pragma unroll
            for (int it = 0; it < 4; it++)
#pragma unroll
                for (int jt = 0; jt < 4; jt++) mma_bf(acc[it][jt], a[it], b[jt]);
        }
        __syncthreads();
        if (i + 2 < nch) load_chunk(s, i + 2);
    }

    float mloc = 0.f;
#pragma unroll
    for (int it = 0; it < 4; it++) {
#pragma unroll
        for (int jt = 0; jt < 4; jt++) {
            const int r0 = crow + mo + it * 16 + (lane >> 2);
            const int gc = ccol + no + jt * 8 + (lane & 3) * 2;
            const int s  = gc >> 8;
            const int j  = gc & 255;
            const int c  = r0 >> 6;
            const int b0 = r0 & 63;
            const int t  = c * 32 + s;
            size_t i0 = ((size_t)b0 * Tt + t) * 256 + j;
            size_t i1 = ((size_t)(b0 + 8) * Tt + t) * 256 + j;
            float2 z0 = *reinterpret_cast<const float2*>(&g_ZB[i0]);
            float2 z1 = *reinterpret_cast<const float2*>(&g_ZB[i1]);
            z0.x += acc[it][jt][0]; z0.y += acc[it][jt][1];
            z1.x += acc[it][jt][2]; z1.y += acc[it][jt][3];
            *reinterpret_cast<float2*>(&g_ZB[i0]) = z0;
            *reinterpret_cast<float2*>(&g_ZB[i1]) = z1;
            mloc = fmaxf(mloc, fmaxf(fmaxf(fabsf(z0.x), fabsf(z0.y)),
                                     fmaxf(fabsf(z1.x), fabsf(z1.y))));
        }
    }
    // fused block max-reduce -> atomic
#pragma unroll
    for (int o = 16; o; o >>= 1) mloc = fmaxf(mloc, __shfl_xor_sync(~0u, mloc, o));
    __shared__ float wm[8];
    if (lane == 0) wm[warp] = mloc;
    __syncthreads();
    if (tid < 8) {
        mloc = wm[tid];
#pragma unroll
        for (int o = 4; o; o >>= 1) mloc = fmaxf(mloc, __shfl_xor_sync(0xff, mloc, o));
        if (tid == 0) atomicMax(&g_maxbits, __float_as_uint(mloc));
    }
}

// ---------------------------------------------------------------------------
// f16 2-product GEMM core (A plain f16, W split f16). 128x128 tile, BK=32,
// 3 smem tiles/stage. occ=2.
// MODE 0: decoder hidden (alpha-scaled bias+act, f16 out)
// MODE 1: decoder final (1/alpha, +bias, fp32 out)
// MODE 2: local scan (triangular K-cut, scatter fp32 store -> g_ZB)
// ---------------------------------------------------------------------------
#define DEC_TILE (128 * PADK * 2)      // 10240 B
#define DEC_STAGE (3 * DEC_TILE)       // 30720 B
#define DEC_SMEM (2 * DEC_STAGE)       // 61440 B

template<int ACT, int MODE>
__global__ __launch_bounds__(256, 2)
void mma_f16g(const __half* __restrict__ A, const __half* __restrict__ Wh,
              const __half* __restrict__ Wl, const float* __restrict__ bias,
              __half* __restrict__ oH, float* __restrict__ oF, int N, int K)
{
    extern __shared__ __align__(16) uint8_t smem8[];
    const int tid  = threadIdx.x;
    const int warp = tid >> 5;
    const int lane = tid & 31;
    const int crow = blockIdx.y * 128;
    const int ccol = blockIdx.x * 128;
    const int mo = (warp >> 2) * 64;
    const int no = (warp & 3) * 32;
    float aSc = 1.f, iSc = 1.f;
    if (MODE == 0) aSc = g_alpha[0];
    if (MODE == 1) iSc = g_alpha[1];

    const __half* gsrc[3] = {
        A + (size_t)crow * K, Wh + (size_t)ccol * K, Wl + (size_t)ccol * K };

    auto load_chunk = [&](int s, int kc) {
        const uint32_t stb = smem_u32(smem8) + s * DEC_STAGE;
#pragma unroll
        for (int q = 0; q < 3; q++) {
            const __half* src = gsrc[q] + kc * 32;
            const uint32_t tb = stb + q * DEC_TILE;
#pragma unroll
            for (int t = 0; t < 2; t++) {
                int g = tid + t * 256;
                int row = g >> 2, c = g & 3;
                cpa16s(tb + row * 80 + c * 16, src + (size_t)row * K + c * 8);
            }
        }
        cpa_commit();
    };

    float acc[4][4][4];
#pragma unroll
    for (int i = 0; i < 4; i++)
#pragma unroll
        for (int j = 0; j < 4; j++)
#pragma unroll
            for (int v = 0; v < 4; v++) acc[i][j][v] = 0.f;

    int Keff = K;
    if (MODE == 2) {
        int s = ccol >> 8;
        int kneed = 16 * (s + 1);
        Keff = (kneed + 31) & ~31;
        if (Keff > K) Keff = K;
    }
    const int nch = Keff / 32;
    load_chunk(0, 0);
    if (nch > 1) load_chunk(1, 1);

    const int a_rowsel = lane & 15;
    const int a_colsel = (lane >> 4) << 3;
    const int b_rowsel = ((lane >> 4) << 3) + (lane & 7);
    const int b_colsel = ((lane >> 3) & 1) << 3;

    for (int i = 0; i < nch; i++) {
        const int s = i & 1;
        if (i + 1 < nch) cpa_wait1(); else cpa_wait0();
        __syncthreads();
        const uint32_t stb = smem_u32(smem8) + s * DEC_STAGE;
        const uint32_t tA  = stb;
        const uint32_t tWh = stb + DEC_TILE;
        const uint32_t tWl = stb + 2 * DEC_TILE;
#pragma unroll
        for (int kk = 0; kk < 2; kk++) {
            const int kc = kk * 16;
            uint32_t a[4][4], b[4][2];
#pragma unroll
            for (int it = 0; it < 4; it++) {
                int row = mo + it * 16 + a_rowsel;
                ldsm4(tA + row * 80 + (kc + a_colsel) * 2,
                      a[it][0], a[it][1], a[it][2], a[it][3]);
            }
#pragma unroll
            for (int jj = 0; jj < 2; jj++) {
                int row = no + jj * 16 + b_rowsel;
                ldsm4(tWh + row * 80 + (kc + b_colsel) * 2,
                      b[2 * jj][0], b[2 * jj][1], b[2 * jj + 1][0], b[2 * jj + 1][1]);
            }
#pragma unroll
            for (int it = 0; it < 4; it++)
#pragma unroll
                for (int jt = 0; jt < 4; jt++) mma_f16(acc[it][jt], a[it], b[jt]);
#pragma unroll
            for (int jj = 0; jj < 2; jj++) {
                int row = no + jj * 16 + b_rowsel;
                ldsm4(tWl + row * 80 + (kc + b_colsel) * 2,
                      b[2 * jj][0], b[2 * jj][1], b[2 * jj + 1][0], b[2 * jj + 1][1]);
            }
#pragma unroll
            for (int it = 0; it < 4; it++)
#pragma unroll
                for (int jt = 0; jt < 4; jt++) mma_f16(acc[it][jt], a[it], b[jt]);
        }
        __syncthreads();
        if (i + 2 < nch) load_chunk(s, i + 2);
    }

#pragma unroll
    for (int it = 0; it < 4; it++) {
#pragma unroll
        for (int jt = 0; jt < 4; jt++) {
            const int r0 = crow + mo + it * 16 + (lane >> 2);
            const int gc = ccol + no + jt * 8 + (lane & 3) * 2;
            if (MODE == 0) {
                const float b0 = bias[gc] * aSc, b1 = bias[gc + 1] * aSc;
                float v00 = acc[it][jt][0] + b0, v01 = acc[it][jt][1] + b1;
                float v10 = acc[it][jt][2] + b0, v11 = acc[it][jt][3] + b1;
                if (ACT) {
                    v00 = (v00 >= 0.f) ? v00 : 0.01f * v00;
                    v01 = (v01 >= 0.f) ? v01 : 0.01f * v01;
                    v10 = (v10 >= 0.f) ? v10 : 0.01f * v10;
                    v11 = (v11 >= 0.f) ? v11 : 0.01f * v11;
                }
                *reinterpret_cast<__half2*>(oH + (size_t)r0 * N + gc) =
                    __halves2half2(__float2half_rn(v00), __float2half_rn(v01));
                *reinterpret_cast<__half2*>(oH + (size_t)(r0 + 8) * N + gc) =
                    __halves2half2(__float2half_rn(v10), __float2half_rn(v11));
            } else if (MODE == 1) {
                const float b0 = bias[gc], b1 = bias[gc + 1];
                float v00 = acc[it][jt][0] * iSc + b0, v01 = acc[it][jt][1] * iSc + b1;
                float v10 = acc[it][jt][2] * iSc + b0, v11 = acc[it][jt][3] * iSc + b1;
                *reinterpret_cast<float2*>(oF + (size_t)r0 * N + gc) = make_float2(v00, v01);
                *reinterpret_cast<float2*>(oF + (size_t)(r0 + 8) * N + gc) = make_float2(v10, v11);
            } else {
                const int s  = gc >> 8;
                const int j  = gc & 255;
                const int c  = r0 >> 6;
                const int b0r = r0 & 63;
                const int t  = c * 32 + s;
                size_t i0 = ((size_t)b0r * Tt + t) * 256 + j;
                size_t i1 = ((size_t)(b0r + 8) * Tt + t) * 256 + j;
                *reinterpret_cast<float2*>(&g_ZB[i0]) =
                    make_float2(acc[it][jt][0], acc[it][jt][1]);
                *reinterpret_cast<float2*>(&g_ZB[i1]) =
                    make_float2(acc[it][jt][2], acc[it][jt][3]);
            }
        }
    }
}

// ---------------------------------------------------------------------------
__global__ void calc_alpha()
{
    float mx = __uint_as_float(g_maxbits);
    int e;
    frexpf(mx, &e);
    float a = exp2f((float)(6 - e));
    g_alpha[0] = a;
    g_alpha[1] = 1.f / a;
}
__global__ void conv_az()
{
    size_t i = ((size_t)blockIdx.x * 256 + threadIdx.x) * 4;
    float a = g_alpha[0];
    float4 v = *reinterpret_cast<const float4*>(&g_ZB[i]);
    *reinterpret_cast<__half2*>(&g_AZ16[i]) =
        __halves2half2(__float2half_rn(v.x * a), __float2half_rn(v.y * a));
    *reinterpret_cast<__half2*>(&g_AZ16[i + 2]) =
        __halves2half2(__float2half_rn(v.z * a), __float2half_rn(v.w * a));
}

// decoder weights: W (K x N fp32) -> Wh/Wl (N x K f16)
__global__ void conv_w16(const float* __restrict__ W, int K, int N,
                         __half* __restrict__ wh, __half* __restrict__ wl)
{
    int idx = blockIdx.x * 256 + threadIdx.x;
    if (idx >= K * N) return;
    int k = idx / N, n = idx % N;
    float v = W[idx];
    __half h = __float2half_rn(v);
    wh[(size_t)n * K + k] = h;
    wl[(size_t)n * K + k] = __float2half_rn(v - __half2float(h));
}

// gather u slices -> U[2048 x 512] plain f16
__global__ void gatherU(const float* __restrict__ in)
{
    int idx = blockIdx.x * 256 + threadIdx.x;
    if (idx >= 2048 * 512) return;
    int m = idx >> 9, k = idx & 511;
    int c = m >> 6, b = m & 63;
    int j = k >> 4, i = k & 15;
    g_Uf[idx] = __float2half_rn(in[((size_t)b * Tt + c * 32 + j) * Din + 272 + i]);
}

// G_r = B_w @ A^r (r=0..31)
__global__ void buildG(const float* __restrict__ Bw)
{
    const int r = blockIdx.x;
    const int n = threadIdx.x;
    if (r == 0) {
        for (int i = 0; i < 16; i++)
            g_G[i * 256 + n] = Bw[i * 256 + n];
        return;
    }
    const float* Ar = g_Apow + (size_t)r * 65536;
    float acc[16];
#pragma unroll
    for (int i = 0; i < 16; i++) acc[i] = 0.f;
    for (int m = 0; m < 256; m++) {
        float a = Ar[m * 256 + n];
#pragma unroll
        for (int i = 0; i < 16; i++)
            acc[i] = fmaf(Bw[i * 256 + m], a, acc[i]);
    }
#pragma unroll
    for (int i = 0; i < 16; i++)
        g_G[(r * 16 + i) * 256 + n] = acc[i];
}

// Wlocal (f16 hi/lo)
__global__ void buildWlocal()
{
    int idx = blockIdx.x * 256 + threadIdx.x;
    if (idx >= 8192 * 512) return;
    int n = idx >> 9, k = idx & 511;
    int s = n >> 8, col = n & 255, j = k >> 4, i = k & 15;
    int r = s - j;
    float v = (r >= 0) ? g_G[(r * 16 + i) * 256 + col] : 0.f;
    __half h = __float2half_rn(v);
    g_Wlh16[idx] = h;
    g_Wll16[idx] = __float2half_rn(v - __half2float(h));
}

__global__ void buildWfix()
{
    int idx = blockIdx.x * 256 + threadIdx.x;
    if (idx >= 8192 * 256) return;
    int n = idx >> 8, k = idx & 255;
    int s = n >> 8, col = n & 255;
    float v = g_Apow[(size_t)(s + 1) * 65536 + k * 256 + col];
    __nv_bfloat16 h = __float2bfloat16(v);
    g_Wfh[idx] = h;
    g_Wfl[idx] = __float2bfloat16(v - __bfloat162float(h));
}

// ---------------------------------------------------------------------------
// Small-M GEMM (encoder, M=64)
// ---------------------------------------------------------------------------
__global__ __launch_bounds__(256)
void gemm_m64(const float* __restrict__ A, long long lda,
              const float* __restrict__ W,
              const float* __restrict__ bias,
              float* __restrict__ C,
              int N, int K, int act)
{
    __shared__ __align__(16) float As[2][16][64];
    __shared__ __align__(16) float Ws[2][16][64];
    const int tid  = threadIdx.x;
    const int ccol = blockIdx.x * 64;
    const int ar = tid >> 2, ak = (tid & 3) * 4;
    const int wr = tid >> 4, wc = (tid & 15) * 4;
    const int ty = tid >> 4, tx = tid & 15;
    float acc[4][4] = {};

    float4 av = *reinterpret_cast<const float4*>(A + (size_t)ar * lda + ak);
    float4 wv = *reinterpret_cast<const float4*>(W + (size_t)wr * N + ccol + wc);
    As[0][ak + 0][ar] = av.x; As[0][ak + 1][ar] = av.y;
    As[0][ak + 2][ar] = av.z; As[0][ak + 3][ar] = av.w;
    *reinterpret_cast<float4*>(&Ws[0][wr][wc]) = wv;
    __syncthreads();

    int buf = 0;
    for (int k0 = 0; k0 < K; k0 += 16) {
        const bool next = (k0 + 16) < K;
        if (next) {
            av = *reinterpret_cast<const float4*>(A + (size_t)ar * lda + k0 + 16 + ak);
            wv = *reinterpret_cast<const float4*>(W + (size_t)(k0 + 16 + wr) * N + ccol + wc);
        }
#pragma unroll
        for (int k = 0; k < 16; k++) {
            float4 a4 = *reinterpret_cast<const float4*>(&As[buf][k][ty * 4]);
            float4 w4 = *reinterpret_cast<const float4*>(&Ws[buf][k][tx * 4]);
            float ar_[4] = {a4.x, a4.y, a4.z, a4.w};
            float wr_[4] = {w4.x, w4.y, w4.z, w4.w};
#pragma unroll
            for (int i = 0; i < 4; i++)
#pragma unroll
                for (int j = 0; j < 4; j++)
                    acc[i][j] = fmaf(ar_[i], wr_[j], acc[i][j]);
        }
        if (next) {
            As[buf ^ 1][ak + 0][ar] = av.x; As[buf ^ 1][ak + 1][ar] = av.y;
            As[buf ^ 1][ak + 2][ar] = av.z; As[buf ^ 1][ak + 3][ar] = av.w;
            *reinterpret_cast<float4*>(&Ws[buf ^ 1][wr][wc]) = wv;
        }
        __syncthreads();
        buf ^= 1;
    }
    float b4[4];
#pragma unroll
    for (int j = 0; j < 4; j++) b4[j] = bias[ccol + tx * 4 + j];
#pragma unroll
    for (int i = 0; i < 4; i++) {
        float o[4];
#pragma unroll
        for (int j = 0; j < 4; j++) {
            float v = acc[i][j] + b4[j];
            if (act) v = (v >= 0.f) ? v : 0.01f * v;
            o[j] = v;
        }
        *reinterpret_cast<float4*>(C + (size_t)(ty * 4 + i) * N + ccol + tx * 4) =
            make_float4(o[0], o[1], o[2], o[3]);
    }
}

__global__ void powinit_kernel(const float* __restrict__ A)
{
    const int i = blockIdx.x * 256 + threadIdx.x;
    g_Apow[65536 + i] = A[i];
    if (blockIdx.x == 0 && threadIdx.x == 0) g_maxbits = 0u;
}

// Apow[half+q] = Apow[half] @ Apow[q]; register-double-buffered loads
__global__ __launch_bounds__(256)
void pow_gemm(int half)
{
    const int q = blockIdx.z + 1;
    const float* S1 = g_Apow + (size_t)half * 65536;
    const float* S2 = g_Apow + (size_t)q * 65536;
    float* D = g_Apow + (size_t)(half + q) * 65536;
    const int ib = blockIdx.y * 64, jb = blockIdx.x * 64;
    __shared__ __align__(16) float As[2][16][64];
    __shared__ __align__(16) float Bs[2][16][64];
    const int tid = threadIdx.x;
    const int ar = tid >> 2, ak = (tid & 3) * 4;
    const int wr = tid >> 4, wc = (tid & 15) * 4;
    const int ty = tid >> 4, tx = tid & 15;
    float acc[4][4] = {};

    float4 av = *reinterpret_cast<const float4*>(S1 + (size_t)(ib + ar) * 256 + ak);
    float4 wv = *reinterpret_cast<const float4*>(S2 + (size_t)wr * 256 + jb + wc);
    As[0][ak + 0][ar] = av.x; As[0][ak + 1][ar] = av.y;
    As[0][ak + 2][ar] = av.z; As[0][ak + 3][ar] = av.w;
    *reinterpret_cast<float4*>(&Bs[0][wr][wc]) = wv;
    __syncthreads();

    int buf = 0;
    for (int k0 = 0; k0 < 256; k0 += 16) {
        const bool next = (k0 + 16) < 256;
        if (next) {
            av = *reinterpret_cast<const float4*>(S1 + (size_t)(ib + ar) * 256 + k0 + 16 + ak);
            wv = *reinterpret_cast<const float4*>(S2 + (size_t)(k0 + 16 + wr) * 256 + jb + wc);
        }
#pragma unroll
        for (int k = 0; k < 16; k++) {
            float4 a4 = *reinterpret_cast<const float4*>(&As[buf][k][ty * 4]);
            float4 w4 = *reinterpret_cast<const float4*>(&Bs[buf][k][tx * 4]);
            float ar_[4] = {a4.x, a4.y, a4.z, a4.w};
            float wr_[4] = {w4.x, w4.y, w4.z, w4.w};
#pragma unroll
            for (int i = 0; i < 4; i++)
#pragma unroll
                for (int j = 0; j < 4; j++)
                    acc[i][j] = fmaf(ar_[i], wr_[j], acc[i][j]);
        }
        if (next) {
            As[buf ^ 1][ak + 0][ar] = av.x; As[buf ^ 1][ak + 1][ar] = av.y;
            As[buf ^ 1][ak + 2][ar] = av.z; As[buf ^ 1][ak + 3][ar] = av.w;
            *reinterpret_cast<float4*>(&Bs[buf ^ 1][wr][wc]) = wv;
        }
        __syncthreads();
        buf ^= 1;
    }
#pragma unroll
    for (int i = 0; i < 4; i++)
        *reinterpret_cast<float4*>(D + (size_t)(ib + ty * 4 + i) * 256 + jb + tx * 4) =
            make_float4(acc[i][0], acc[i][1], acc[i][2], acc[i][3]);
}

// carry chain: 64 blocks, 4-way accumulators, unroll 4, fused bf16 split out
__global__ void carry_chain64(const float* __restrict__ z0)
{
    const int b = blockIdx.x;
    const int j = threadIdx.x;
    __shared__ float cp[256];
    float cur = z0[b * 256 + j];
    cp[j] = cur;
    {
        __nv_bfloat16 h = __float2bfloat16(cur);
        g_Ch[(size_t)b * 256 + j] = h;
        g_Cl[(size_t)b * 256 + j] = __float2bfloat16(cur - __bfloat162float(h));
    }
    __syncthreads();
    const float* A32 = g_Apow + (size_t)32 * 65536;
    for (int c = 1; c < 32; c++) {
        float s0 = g_ZB[((size_t)b * Tt + c * 32 - 1) * 256 + j];
        float s1 = 0.f, s2 = 0.f, s3 = 0.f;
#pragma unroll 4
        for (int k = 0; k < 256; k += 4) {
            s0 = fmaf(cp[k + 0], A32[(size_t)(k + 0) * 256 + j], s0);
            s1 = fmaf(cp[k + 1], A32[(size_t)(k + 1) * 256 + j], s1);
            s2 = fmaf(cp[k + 2], A32[(size_t)(k + 2) * 256 + j], s2);
            s3 = fmaf(cp[k + 3], A32[(size_t)(k + 3) * 256 + j], s3);
        }
        float a = (s0 + s1) + (s2 + s3);
        __syncthreads();
        cp[j] = a;
        __nv_bfloat16 h = __float2bfloat16(a);
        g_Ch[((size_t)c * 64 + b) * 256 + j] = h;
        g_Cl[((size_t)c * 64 + b) * 256 + j] = __float2bfloat16(a - __bfloat162float(h));
        __syncthreads();
    }
}

// ---------------------------------------------------------------------------
extern "C" void kernel_launch(void* const* d_in, const int* in_sizes, int n_in,
                              void* d_out, int out_size)
{
    const float* in  = (const float*)d_in[0];
    const float* ew1 = (const float*)d_in[1];
    const float* eb1 = (const float*)d_in[2];
    const float* ew2 = (const float*)d_in[3];
    const float* eb2 = (const float*)d_in[4];
    const float* ew3 = (const float*)d_in[5];
    const float* eb3 = (const float*)d_in[6];
    const float* Aw  = (const float*)d_in[7];
    const float* Bw  = (const float*)d_in[8];
    const float* dw1 = (const float*)d_in[9];
    const float* db1 = (const float*)d_in[10];
    const float* dw2 = (const float*)d_in[11];
    const float* db2 = (const float*)d_in[12];
    const float* dw3 = (const float*)d_in[13];
    const float* db3 = (const float*)d_in[14];
    float* out = (float*)d_out;

    void *ph1, *ph2, *ph1e, *ph2e, *pz0, *paz;
    void *pw1h, *pw1l, *pw2h, *pw2l, *pw3h, *pw3l;
    void *puf, *pwlh, *pwll, *pwfh, *pwfl, *pch, *pcl;
    cudaGetSymbolAddress(&ph1, g_H1);
    cudaGetSymbolAddress(&ph2, g_H2);
    cudaGetSymbolAddress(&ph1e, g_h1e);
    cudaGetSymbolAddress(&ph2e, g_h2e);
    cudaGetSymbolAddress(&pz0, g_z0);
    cudaGetSymbolAddress(&paz, g_AZ16);
    cudaGetSymbolAddress(&pw1h, g_W1h);
    cudaGetSymbolAddress(&pw1l, g_W1l);
    cudaGetSymbolAddress(&pw2h, g_W2h);
    cudaGetSymbolAddress(&pw2l, g_W2l);
    cudaGetSymbolAddress(&pw3h, g_W3h);
    cudaGetSymbolAddress(&pw3l, g_W3l);
    cudaGetSymbolAddress(&puf, g_Uf);
    cudaGetSymbolAddress(&pwlh, g_Wlh16);
    cudaGetSymbolAddress(&pwll, g_Wll16);
    cudaGetSymbolAddress(&pwfh, g_Wfh);
    cudaGetSymbolAddress(&pwfl, g_Wfl);
    cudaGetSymbolAddress(&pch, g_Ch);
    cudaGetSymbolAddress(&pcl, g_Cl);
    float* h1e = (float*)ph1e;
    float* h2e = (float*)ph2e;
    float* z0  = (float*)pz0;
    __half* AZ = (__half*)paz;
    __half* H1 = (__half*)ph1;
    __half* H2 = (__half*)ph2;

    cudaFuncSetAttribute(mma_fix, cudaFuncAttributeMaxDynamicSharedMemorySize, MMA_SMEM);
    cudaFuncSetAttribute(mma_f16g<1, 0>, cudaFuncAttributeMaxDynamicSharedMemorySize, DEC_SMEM);
    cudaFuncSetAttribute(mma_f16g<0, 1>, cudaFuncAttributeMaxDynamicSharedMemorySize, DEC_SMEM);
    cudaFuncSetAttribute(mma_f16g<0, 2>, cudaFuncAttributeMaxDynamicSharedMemorySize, DEC_SMEM);

    // streams/events created once, outside graph capture
    static cudaStream_t s1 = nullptr;
    static cudaEvent_t eFork = nullptr, eU = nullptr, eEnc = nullptr, eSide = nullptr;
    if (!s1) {
        cudaStreamCreateWithFlags(&s1, cudaStreamNonBlocking);
        cudaEventCreateWithFlags(&eFork, cudaEventDisableTiming);
        cudaEventCreateWithFlags(&eU, cudaEventDisableTiming);
        cudaEventCreateWithFlags(&eEnc, cudaEventDisableTiming);
        cudaEventCreateWithFlags(&eSide, cudaEventDisableTiming);
    }

    // ---- fork side stream ----
    cudaEventRecord(eFork, 0);
    cudaStreamWaitEvent(s1, eFork, 0);

    // side stream: gatherU -> encoder -> decoder weight conversions
    gatherU<<<(2048 * 512) / 256, 256, 0, s1>>>(in);
    cudaEventRecord(eU, s1);
    gemm_m64<<<ENCD / 64, 256, 0, s1>>>(in, (long long)Tt * Din, ew1, eb1, h1e, ENCD, 256, 1);
    gemm_m64<<<ENCD / 64, 256, 0, s1>>>(h1e, ENCD, ew2, eb2, h2e, ENCD, ENCD, 1);
    gemm_m64<<<LAT / 64, 256, 0, s1>>>(h2e, ENCD, ew3, eb3, z0, LAT, ENCD, 1);
    cudaEventRecord(eEnc, s1);
    conv_w16<<<(256 * 512 + 255) / 256, 256, 0, s1>>>(dw1, 256, 512, (__half*)pw1h, (__half*)pw1l);
    conv_w16<<<(512 * 512 + 255) / 256, 256, 0, s1>>>(dw2, 512, 512, (__half*)pw2h, (__half*)pw2l);
    conv_w16<<<(512 * 256 + 255) / 256, 256, 0, s1>>>(dw3, 512, 256, (__half*)pw3h, (__half*)pw3l);
    cudaEventRecord(eSide, s1);

    // main stream: A powers -> scan operand builds
    powinit_kernel<<<256, 256>>>(Aw);
    for (int half = 1; half <= 16; half <<= 1)
        pow_gemm<<<dim3(4, 4, half), 256>>>(half);
    buildG<<<32, 256>>>(Bw);
    buildWfix<<<(8192 * 256) / 256, 256>>>();
    buildWlocal<<<(8192 * 512) / 256, 256>>>();

    // chunk-local scan as ONE f16 2-product GEMM (triangular K-cut) -> g_ZB
    cudaStreamWaitEvent(0, eU, 0);
    mma_f16g<0, 2><<<dim3(64, 16), 256, DEC_SMEM>>>(
        (__half*)puf, (__half*)pwlh, (__half*)pwll, nullptr,
        nullptr, nullptr, 8192, 512);

    // carry chain (fused bf16 split out)
    cudaStreamWaitEvent(0, eEnc, 0);
    carry_chain64<<<64, 256>>>(z0);

    // fused fix GEMM (bf16 3-product): + g_ZB, fused max-|z| reduce
    mma_fix<<<dim3(64, 16), 256, MMA_SMEM>>>(
        (__nv_bfloat16*)pch, (__nv_bfloat16*)pcl,
        (__nv_bfloat16*)pwfh, (__nv_bfloat16*)pwfl, 8192, 256);

    // dynamic scale: alpha -> f16 convert
    calc_alpha<<<1, 1>>>();
    conv_az<<<16384, 256>>>();

    // decoder (f16 2-product, alpha-scaled)
    cudaStreamWaitEvent(0, eSide, 0);
    mma_f16g<1, 0><<<dim3(ENCD / 128, NROWS / 128), 256, DEC_SMEM>>>(
        AZ, (__half*)pw1h, (__half*)pw1l, db1, H1, nullptr, ENCD, LAT);
    mma_f16g<1, 0><<<dim3(ENCD / 128, NROWS / 128), 256, DEC_SMEM>>>(
        H1, (__half*)pw2h, (__half*)pw2l, db2, H2, nullptr, ENCD, ENCD);
    mma_f16g<0, 1><<<dim3(LAT / 128, NROWS / 128), 256, DEC_SMEM>>>(
        H2, (__half*)pw3h, (__half*)pw3l, db3, nullptr, out, LAT, ENCD);
}